// round 1
// baseline (speedup 1.0000x reference)
#include <cuda_runtime.h>

#define D 512
#define HEADS 8
#define HD 64
#define TSEQ 1024
#define CHUNK 128
#define NC (TSEQ / CHUNK)   // 8
#define MAXB 4

// ---------------- scratch (no allocations allowed) ----------------
__device__ float g_q[MAXB * TSEQ * D];
__device__ float g_k[MAXB * TSEQ * D];
__device__ float g_v[MAXB * TSEQ * D];
__device__ float g_attn[MAXB * TSEQ * D];
__device__ float g_ckv[MAXB * HEADS * NC * HD * HD];
__device__ float g_cks[MAXB * HEADS * NC * HD];

// ---------------- GEMM: C[n,j] = sum_k A[n,k] * W[j,k] + bias[j] ----------------
// BM=128, BN=128, BK=16, 256 threads, 8x8 register tile per thread.
#define BM 128
#define BN 128
#define BK 16
#define LDP 132   // padded smem row length (floats), 16B-aligned stride

__global__ void __launch_bounds__(256) gemm_kernel(
    const float* __restrict__ Aext, const float* __restrict__ W,
    const float* __restrict__ bias, float* __restrict__ Oext,
    int asel, int osel, int act)
{
    __shared__ __align__(16) float As[BK][LDP];
    __shared__ __align__(16) float Bs[BK][LDP];

    const float* A = (asel == 0) ? Aext : g_attn;
    float* O = (osel == 3) ? Oext : (osel == 0 ? g_q : (osel == 1 ? g_k : g_v));

    int tid = threadIdx.x;
    int tx = tid & 15, ty = tid >> 4;
    int rowBase = blockIdx.y * BM;
    int colBase = blockIdx.x * BN;

    float acc[8][8];
#pragma unroll
    for (int i = 0; i < 8; i++)
#pragma unroll
        for (int j = 0; j < 8; j++) acc[i][j] = 0.f;

    for (int k0 = 0; k0 < D; k0 += BK) {
#pragma unroll
        for (int it = 0; it < 8; it++) {
            int lin = tid + it * 256;       // 0..2047
            int r = lin >> 4;               // 0..127
            int kk = lin & 15;
            As[kk][r] = A[(size_t)(rowBase + r) * D + k0 + kk];
            Bs[kk][r] = W[(size_t)(colBase + r) * D + k0 + kk];
        }
        __syncthreads();
#pragma unroll
        for (int kk = 0; kk < BK; kk++) {
            float4 a0 = *(const float4*)&As[kk][ty * 8];
            float4 a1 = *(const float4*)&As[kk][ty * 8 + 4];
            float4 b0 = *(const float4*)&Bs[kk][tx * 8];
            float4 b1 = *(const float4*)&Bs[kk][tx * 8 + 4];
            float a[8] = {a0.x, a0.y, a0.z, a0.w, a1.x, a1.y, a1.z, a1.w};
            float b[8] = {b0.x, b0.y, b0.z, b0.w, b1.x, b1.y, b1.z, b1.w};
#pragma unroll
            for (int i = 0; i < 8; i++)
#pragma unroll
                for (int j = 0; j < 8; j++) acc[i][j] += a[i] * b[j];
        }
        __syncthreads();
    }

#pragma unroll
    for (int i = 0; i < 8; i++) {
        int r = rowBase + ty * 8 + i;
#pragma unroll
        for (int j = 0; j < 8; j++) {
            int c = colBase + tx * 8 + j;
            float v = acc[i][j] + bias[c];
            if (act) v = (v > 0.f) ? (v + 1.f) : __expf(v);   // elu(v)+1
            O[(size_t)r * D + c] = v;
        }
    }
}

// ---------------- per-chunk local sums: KV_local[d][m], ksum_local[d] ----------------
__global__ void __launch_bounds__(256) chunk_sum_kernel()
{
    int bc = blockIdx.x;            // b*NC + c
    int h = blockIdx.y;
    int b = bc / NC, c = bc % NC;
    extern __shared__ __align__(16) float sm0[];
    float* ks = sm0;                 // [CHUNK][HD]
    float* vs = sm0 + CHUNK * HD;    // [CHUNK][HD]

    int tid = threadIdx.x;
    size_t nbase = (size_t)b * TSEQ + (size_t)c * CHUNK;

#pragma unroll
    for (int it = 0; it < 8; it++) {
        int lin = tid + it * 256;   // float4 index, 2048 total
        int t = lin >> 4;
        int d4 = lin & 15;
        size_t g = (nbase + t) * D + h * HD + d4 * 4;
        ((float4*)ks)[t * 16 + d4] = *(const float4*)&g_k[g];
        ((float4*)vs)[t * 16 + d4] = *(const float4*)&g_v[g];
    }
    __syncthreads();

    int d0 = (tid >> 4) * 4;
    int m0 = (tid & 15) * 4;
    float acc[4][4];
#pragma unroll
    for (int i = 0; i < 4; i++)
#pragma unroll
        for (int j = 0; j < 4; j++) acc[i][j] = 0.f;

#pragma unroll 4
    for (int t = 0; t < CHUNK; t++) {
        float4 kd = *(const float4*)&ks[t * HD + d0];
        float4 vm = *(const float4*)&vs[t * HD + m0];
        float ka[4] = {kd.x, kd.y, kd.z, kd.w};
        float va[4] = {vm.x, vm.y, vm.z, vm.w};
#pragma unroll
        for (int i = 0; i < 4; i++)
#pragma unroll
            for (int j = 0; j < 4; j++) acc[i][j] += ka[i] * va[j];
    }

    size_t sidx = ((size_t)(b * HEADS + h) * NC + c);
    float* ckv = g_ckv + sidx * HD * HD;
#pragma unroll
    for (int i = 0; i < 4; i++)
#pragma unroll
        for (int j = 0; j < 4; j++) ckv[(d0 + i) * HD + m0 + j] = acc[i][j];

    if (tid < HD) {
        float s = 0.f;
        for (int t = 0; t < CHUNK; t++) s += ks[t * HD + tid];
        g_cks[sidx * HD + tid] = s;
    }
}

// ---------------- exclusive prefix over chunks per (b,h) ----------------
__global__ void __launch_bounds__(256) prefix_kernel()
{
    int bh = blockIdx.x;
    int tid = threadIdx.x;
    float* base = g_ckv + (size_t)bh * NC * HD * HD;
    for (int e = tid; e < HD * HD; e += 256) {
        float carry = 0.f;
#pragma unroll
        for (int c = 0; c < NC; c++) {
            float tv = base[c * HD * HD + e];
            base[c * HD * HD + e] = carry;
            carry += tv;
        }
    }
    if (tid < HD) {
        float* kb = g_cks + (size_t)bh * NC * HD;
        float carry = 0.f;
#pragma unroll
        for (int c = 0; c < NC; c++) {
            float tv = kb[c * HD + tid];
            kb[c * HD + tid] = carry;
            carry += tv;
        }
    }
}

// ---------------- per-chunk attention ----------------
// S = mask(Q Kt), O = S V + Q KVp, denom = rowsum(S) + Q . ksum
#define QP 132
#define VP 68
#define QT_OFF 0
#define KT_OFF (HD * QP)                 // 8448
#define V_OFF  (KT_OFF + HD * QP)        // 16896
#define S_OFF  (V_OFF + CHUNK * VP)      // 25600
#define KVP_OFF (S_OFF + CHUNK * QP)     // 42496
#define KS_OFF (KVP_OFF + HD * VP)       // 46848
#define DN_OFF (KS_OFF + HD)             // 46912
#define SM2C_FLOATS (DN_OFF + CHUNK)     // 47040 floats = 188160 B

__global__ void __launch_bounds__(256) attn_chunk_kernel()
{
    int bc = blockIdx.x;
    int h = blockIdx.y;
    int b = bc / NC, c = bc % NC;
    extern __shared__ __align__(16) float sm[];
    float* Qt = sm + QT_OFF;     // [HD][QP]  (transposed: [d][i])
    float* Kt = sm + KT_OFF;     // [HD][QP]
    float* V  = sm + V_OFF;      // [CHUNK][VP]
    float* S  = sm + S_OFF;      // [CHUNK][QP] row-major [i][j]
    float* KVp = sm + KVP_OFF;   // [HD][VP]
    float* ksum = sm + KS_OFF;   // [HD]
    float* dn = sm + DN_OFF;     // [CHUNK]

    int tid = threadIdx.x;
    int tx = tid & 15, ty = tid >> 4;
    size_t nbase = (size_t)b * TSEQ + (size_t)c * CHUNK;
    size_t sidx = ((size_t)(b * HEADS + h) * NC + c);

    // loads (coalesced global, transposed store for Q/K)
#pragma unroll
    for (int it = 0; it < 32; it++) {
        int lin = tid + it * 256;    // 8192
        int i = lin >> 6, d = lin & 63;
        size_t g = (nbase + i) * D + h * HD + d;
        Qt[d * QP + i] = g_q[g];
        Kt[d * QP + i] = g_k[g];
    }
#pragma unroll
    for (int it = 0; it < 8; it++) {
        int lin = tid + it * 256;    // float4, 2048
        int i = lin >> 4, d4 = lin & 15;
        *(float4*)&V[i * VP + d4 * 4] =
            *(const float4*)&g_v[(nbase + i) * D + h * HD + d4 * 4];
    }
#pragma unroll
    for (int it = 0; it < 16; it++) {
        int lin = tid + it * 256;    // 4096
        int dd = lin >> 6, m = lin & 63;
        KVp[dd * VP + m] = g_ckv[sidx * HD * HD + lin];
    }
    if (tid < HD) ksum[tid] = g_cks[sidx * HD + tid];
    __syncthreads();

    // ---- stage 1: S = mask(Q K^T) ----
    {
        int i0 = ty * 8, j0 = tx * 8;
        float s[8][8];
#pragma unroll
        for (int i = 0; i < 8; i++)
#pragma unroll
            for (int j = 0; j < 8; j++) s[i][j] = 0.f;

#pragma unroll 8
        for (int d = 0; d < HD; d++) {
            float4 q0 = *(const float4*)&Qt[d * QP + i0];
            float4 q1 = *(const float4*)&Qt[d * QP + i0 + 4];
            float4 k0 = *(const float4*)&Kt[d * QP + j0];
            float4 k1 = *(const float4*)&Kt[d * QP + j0 + 4];
            float qa[8] = {q0.x, q0.y, q0.z, q0.w, q1.x, q1.y, q1.z, q1.w};
            float kb[8] = {k0.x, k0.y, k0.z, k0.w, k1.x, k1.y, k1.z, k1.w};
#pragma unroll
            for (int i = 0; i < 8; i++)
#pragma unroll
                for (int j = 0; j < 8; j++) s[i][j] += qa[i] * kb[j];
        }
        // causal mask (local since same chunk) + vectorized row-major store
#pragma unroll
        for (int ii = 0; ii < 8; ii++) {
            int i = i0 + ii;
            float4 o0, o1;
            o0.x = (j0 + 0 <= i) ? s[ii][0] : 0.f;
            o0.y = (j0 + 1 <= i) ? s[ii][1] : 0.f;
            o0.z = (j0 + 2 <= i) ? s[ii][2] : 0.f;
            o0.w = (j0 + 3 <= i) ? s[ii][3] : 0.f;
            o1.x = (j0 + 4 <= i) ? s[ii][4] : 0.f;
            o1.y = (j0 + 5 <= i) ? s[ii][5] : 0.f;
            o1.z = (j0 + 6 <= i) ? s[ii][6] : 0.f;
            o1.w = (j0 + 7 <= i) ? s[ii][7] : 0.f;
            *(float4*)&S[i * QP + j0] = o0;
            *(float4*)&S[i * QP + j0 + 4] = o1;
        }
    }
    __syncthreads();

    // ---- stage 2: O = S V + Q KVp ; denom ----
    {
        int i0 = ty * 8, m0 = tx * 4;
        float acc[8][4];
        float rs[8];
#pragma unroll
        for (int i = 0; i < 8; i++) {
            rs[i] = 0.f;
#pragma unroll
            for (int j = 0; j < 4; j++) acc[i][j] = 0.f;
        }

#pragma unroll 4
        for (int j = 0; j < CHUNK; j++) {
            float4 vv = *(const float4*)&V[j * VP + m0];
            float va[4] = {vv.x, vv.y, vv.z, vv.w};
#pragma unroll
            for (int ii = 0; ii < 8; ii++) {
                float sv = S[(i0 + ii) * QP + j];
                rs[ii] += sv;
#pragma unroll
                for (int mm = 0; mm < 4; mm++) acc[ii][mm] += sv * va[mm];
            }
        }
#pragma unroll 4
        for (int d = 0; d < HD; d++) {
            float4 q0 = *(const float4*)&Qt[d * QP + i0];
            float4 q1 = *(const float4*)&Qt[d * QP + i0 + 4];
            float qa[8] = {q0.x, q0.y, q0.z, q0.w, q1.x, q1.y, q1.z, q1.w};
            float4 kv = *(const float4*)&KVp[d * VP + m0];
            float ka[4] = {kv.x, kv.y, kv.z, kv.w};
            float kss = ksum[d];
#pragma unroll
            for (int ii = 0; ii < 8; ii++) {
                rs[ii] += qa[ii] * kss;
#pragma unroll
                for (int mm = 0; mm < 4; mm++) acc[ii][mm] += qa[ii] * ka[mm];
            }
        }
        if (tx == 0) {
#pragma unroll
            for (int ii = 0; ii < 8; ii++) dn[i0 + ii] = rs[ii];
        }
        __syncthreads();
#pragma unroll
        for (int ii = 0; ii < 8; ii++) {
            float inv = 1.f / fmaxf(dn[i0 + ii], 1e-6f);
            size_t g = (nbase + i0 + ii) * D + h * HD + m0;
#pragma unroll
            for (int mm = 0; mm < 4; mm++) g_attn[g + mm] = acc[ii][mm] * inv;
        }
    }
}

// ---------------- launch ----------------
extern "C" void kernel_launch(void* const* d_in, const int* in_sizes, int n_in,
                              void* d_out, int out_size)
{
    const float* x  = (const float*)d_in[0];
    const float* Wq = (const float*)d_in[1];
    const float* bq = (const float*)d_in[2];
    const float* Wk = (const float*)d_in[3];
    const float* bk = (const float*)d_in[4];
    const float* Wv = (const float*)d_in[5];
    const float* bv = (const float*)d_in[6];
    const float* Wo = (const float*)d_in[7];
    const float* bo = (const float*)d_in[8];

    int N = in_sizes[0] / D;     // b * t
    int B = N / TSEQ;

    cudaFuncSetAttribute(chunk_sum_kernel,
                         cudaFuncAttributeMaxDynamicSharedMemorySize,
                         2 * CHUNK * HD * (int)sizeof(float));
    cudaFuncSetAttribute(attn_chunk_kernel,
                         cudaFuncAttributeMaxDynamicSharedMemorySize,
                         SM2C_FLOATS * (int)sizeof(float));

    dim3 ggrid(D / BN, N / BM);
    gemm_kernel<<<ggrid, 256>>>(x, Wq, bq, nullptr, 0, 0, 1);
    gemm_kernel<<<ggrid, 256>>>(x, Wk, bk, nullptr, 0, 1, 1);
    gemm_kernel<<<ggrid, 256>>>(x, Wv, bv, nullptr, 0, 2, 0);

    chunk_sum_kernel<<<dim3(B * NC, HEADS), 256,
                       2 * CHUNK * HD * sizeof(float)>>>();
    prefix_kernel<<<B * HEADS, 256>>>();
    attn_chunk_kernel<<<dim3(B * NC, HEADS), 256,
                        SM2C_FLOATS * sizeof(float)>>>();

    gemm_kernel<<<ggrid, 256>>>(nullptr, Wo, bo, (float*)d_out, 1, 3, 0);
}

// round 6
// speedup vs baseline: 2.9800x; 2.9800x over previous
// R5 retry: identical theory to R4 (opaque container failure matched the R0
// empty-stub flake signature; kernel audited clean — no loops that can hang,
// no OOB, mma.sync is legal on target sm_100).
#include <cuda_runtime.h>
#include <cuda_bf16.h>
#include <cstdint>

#define D 512
#define HEADS 8
#define HD 64
#define TSEQ 1024
#define CHUNK 128
#define NC (TSEQ / CHUNK)   // 8
#define MAXB 4

// ---------------- scratch (no allocations allowed) ----------------
__device__ float g_q[MAXB * TSEQ * D];
__device__ float g_k[MAXB * TSEQ * D];
__device__ float g_v[MAXB * TSEQ * D];
__device__ float g_ckv[MAXB * HEADS * NC * HD * HD];
__device__ float g_cks[MAXB * HEADS * NC * HD];
// bf16 split operands
__device__ __nv_bfloat16 g_whi[4 * D * D];
__device__ __nv_bfloat16 g_wlo[4 * D * D];
__device__ __nv_bfloat16 g_xhi[MAXB * TSEQ * D];
__device__ __nv_bfloat16 g_xlo[MAXB * TSEQ * D];
__device__ __nv_bfloat16 g_phi[MAXB * TSEQ * D];   // post-attention activations
__device__ __nv_bfloat16 g_plo[MAXB * TSEQ * D];

// ---------------- helpers ----------------
__device__ __forceinline__ void split2(float f, uint16_t& h, uint16_t& l) {
    __nv_bfloat16 hb = __float2bfloat16_rn(f);
    float hf = __bfloat162float(hb);
    __nv_bfloat16 lb = __float2bfloat16_rn(f - hf);
    h = __bfloat16_as_ushort(hb);
    l = __bfloat16_as_ushort(lb);
}

__device__ __forceinline__ void mma_bf16(float* d, const uint32_t* a, const uint32_t* b) {
    asm volatile(
        "mma.sync.aligned.m16n8k16.row.col.f32.bf16.bf16.f32 "
        "{%0,%1,%2,%3}, {%4,%5,%6,%7}, {%8,%9}, {%0,%1,%2,%3};"
        : "+f"(d[0]), "+f"(d[1]), "+f"(d[2]), "+f"(d[3])
        : "r"(a[0]), "r"(a[1]), "r"(a[2]), "r"(a[3]), "r"(b[0]), "r"(b[1]));
}

// ---------------- conversion kernels ----------------
__global__ void __launch_bounds__(256) convert_w(
    const float* __restrict__ Wq, const float* __restrict__ Wk,
    const float* __restrict__ Wv, const float* __restrict__ Wo)
{
    int e4 = blockIdx.x * 256 + threadIdx.x;       // 0..262143 (4 * 65536)
    int w = e4 >> 16;
    int off = e4 & 65535;
    const float* src = (w == 0) ? Wq : (w == 1) ? Wk : (w == 2) ? Wv : Wo;
    float4 v = ((const float4*)src)[off];
    float f[4] = {v.x, v.y, v.z, v.w};
    uint16_t h[4], l[4];
#pragma unroll
    for (int j = 0; j < 4; ++j) split2(f[j], h[j], l[j]);
    ((uint2*)(g_whi + (size_t)w * D * D))[off] =
        make_uint2((uint32_t)h[0] | ((uint32_t)h[1] << 16),
                   (uint32_t)h[2] | ((uint32_t)h[3] << 16));
    ((uint2*)(g_wlo + (size_t)w * D * D))[off] =
        make_uint2((uint32_t)l[0] | ((uint32_t)l[1] << 16),
                   (uint32_t)l[2] | ((uint32_t)l[3] << 16));
}

__global__ void __launch_bounds__(256) convert_x(const float* __restrict__ src, int n4)
{
    int i = blockIdx.x * 256 + threadIdx.x;
    if (i >= n4) return;
    float4 v = ((const float4*)src)[i];
    float f[4] = {v.x, v.y, v.z, v.w};
    uint16_t h[4], l[4];
#pragma unroll
    for (int j = 0; j < 4; ++j) split2(f[j], h[j], l[j]);
    ((uint2*)g_xhi)[i] = make_uint2((uint32_t)h[0] | ((uint32_t)h[1] << 16),
                                    (uint32_t)h[2] | ((uint32_t)h[3] << 16));
    ((uint2*)g_xlo)[i] = make_uint2((uint32_t)l[0] | ((uint32_t)l[1] << 16),
                                    (uint32_t)l[2] | ((uint32_t)l[3] << 16));
}

// ---------------- mma.sync split-bf16 GEMM ----------------
// C[n,j] = sum_k A[n,k] * W[j,k] + bias[j], optional elu+1.
// A,W given as pre-split bf16 hi/lo. Tile 128x128, KC=64, double-buffered.
// smem layout per buffer (u32 units, stride 36 per row of 32 u32):
//   AHI[128][36], ALO, BHI, BLO  -> 4*4608 = 18432 u32/buffer, 2 buffers.
#define ROWU 36
#define ARRU (128 * ROWU)      // 4608
#define BUFU (4 * ARRU)        // 18432
#define GEMM_SMEM (2 * BUFU * 4)   // 147456 bytes

__device__ __forceinline__ void load_chunk(
    uint32_t* dst, const uint32_t* Ahi, const uint32_t* Alo,
    const uint32_t* Bhi, const uint32_t* Blo,
    int rowBase, int colBase, int k0u, int tid)
{
    // each array: 128 rows x 8 uint4
#pragma unroll
    for (int it = 0; it < 4; ++it) {
        int lin = tid + it * 256;          // 0..1023
        int r = lin >> 3, q = lin & 7;
        uint4 v = *(const uint4*)(Ahi + (size_t)(rowBase + r) * 256 + k0u + q * 4);
        *(uint4*)(dst + r * ROWU + q * 4) = v;
    }
#pragma unroll
    for (int it = 0; it < 4; ++it) {
        int lin = tid + it * 256;
        int r = lin >> 3, q = lin & 7;
        uint4 v = *(const uint4*)(Alo + (size_t)(rowBase + r) * 256 + k0u + q * 4);
        *(uint4*)(dst + ARRU + r * ROWU + q * 4) = v;
    }
#pragma unroll
    for (int it = 0; it < 4; ++it) {
        int lin = tid + it * 256;
        int r = lin >> 3, q = lin & 7;
        uint4 v = *(const uint4*)(Bhi + (size_t)(colBase + r) * 256 + k0u + q * 4);
        *(uint4*)(dst + 2 * ARRU + r * ROWU + q * 4) = v;
    }
#pragma unroll
    for (int it = 0; it < 4; ++it) {
        int lin = tid + it * 256;
        int r = lin >> 3, q = lin & 7;
        uint4 v = *(const uint4*)(Blo + (size_t)(colBase + r) * 256 + k0u + q * 4);
        *(uint4*)(dst + 3 * ARRU + r * ROWU + q * 4) = v;
    }
}

__global__ void __launch_bounds__(256, 1) mma_gemm(
    int asel, int wBase, int oselBase,
    const float* __restrict__ bias0, const float* __restrict__ bias1,
    const float* __restrict__ bias2,
    float* __restrict__ Oext, int actmask)
{
    extern __shared__ __align__(16) uint32_t smu[];
    int tid = threadIdx.x, lane = tid & 31, wid = tid >> 5;
    int warpRow = wid >> 2;   // 0..1  (64 rows each)
    int warpCol = wid & 3;    // 0..3  (32 cols each)
    int z = blockIdx.z;
    int rowBase = blockIdx.y * 128;
    int colBase = blockIdx.x * 128;

    const uint32_t* Ahi = asel ? (const uint32_t*)g_phi : (const uint32_t*)g_xhi;
    const uint32_t* Alo = asel ? (const uint32_t*)g_plo : (const uint32_t*)g_xlo;
    int wz = wBase + z;
    const uint32_t* Bhi = (const uint32_t*)g_whi + (size_t)wz * (D * D / 2);
    const uint32_t* Blo = (const uint32_t*)g_wlo + (size_t)wz * (D * D / 2);
    const float* bias = (z == 0) ? bias0 : (z == 1) ? bias1 : bias2;
    int osel = oselBase + z;
    float* O = (osel == 3) ? Oext : (osel == 0 ? g_q : (osel == 1 ? g_k : g_v));
    int act = (actmask >> z) & 1;

    float acc[4][4][4];
#pragma unroll
    for (int mt = 0; mt < 4; ++mt)
#pragma unroll
        for (int nt = 0; nt < 4; ++nt)
#pragma unroll
            for (int r = 0; r < 4; ++r) acc[mt][nt][r] = 0.f;

    load_chunk(smu, Ahi, Alo, Bhi, Blo, rowBase, colBase, 0, tid);
    __syncthreads();

    for (int c = 0; c < 8; ++c) {
        int buf = c & 1;
        if (c < 7)
            load_chunk(smu + ((c + 1) & 1) * BUFU, Ahi, Alo, Bhi, Blo,
                       rowBase, colBase, (c + 1) * 32, tid);

        const uint32_t* AH = smu + buf * BUFU;
        const uint32_t* AL = AH + ARRU;
        const uint32_t* BH = AH + 2 * ARRU;
        const uint32_t* BL = AH + 3 * ARRU;
#pragma unroll
        for (int ks = 0; ks < 4; ++ks) {
            int kpb = ks * 8 + (lane & 3);
            uint32_t ahi[4][4], alo[4][4], bhi[4][2], blo[4][2];
#pragma unroll
            for (int mt = 0; mt < 4; ++mt) {
                int r0 = (warpRow * 64 + mt * 16 + (lane >> 2)) * ROWU;
                ahi[mt][0] = AH[r0 + kpb];
                ahi[mt][1] = AH[r0 + 8 * ROWU + kpb];
                ahi[mt][2] = AH[r0 + kpb + 4];
                ahi[mt][3] = AH[r0 + 8 * ROWU + kpb + 4];
                alo[mt][0] = AL[r0 + kpb];
                alo[mt][1] = AL[r0 + 8 * ROWU + kpb];
                alo[mt][2] = AL[r0 + kpb + 4];
                alo[mt][3] = AL[r0 + 8 * ROWU + kpb + 4];
            }
#pragma unroll
            for (int nt = 0; nt < 4; ++nt) {
                int n0 = (warpCol * 32 + nt * 8 + (lane >> 2)) * ROWU;
                bhi[nt][0] = BH[n0 + kpb];
                bhi[nt][1] = BH[n0 + kpb + 4];
                blo[nt][0] = BL[n0 + kpb];
                blo[nt][1] = BL[n0 + kpb + 4];
            }
#pragma unroll
            for (int mt = 0; mt < 4; ++mt)
#pragma unroll
                for (int nt = 0; nt < 4; ++nt) {
                    mma_bf16(acc[mt][nt], ahi[mt], bhi[nt]);
                    mma_bf16(acc[mt][nt], ahi[mt], blo[nt]);
                    mma_bf16(acc[mt][nt], alo[mt], bhi[nt]);
                }
        }
        __syncthreads();
    }

    // epilogue: bias + optional elu+1, direct stores
#pragma unroll
    for (int mt = 0; mt < 4; ++mt) {
        int r0 = rowBase + warpRow * 64 + mt * 16 + (lane >> 2);
#pragma unroll
        for (int nt = 0; nt < 4; ++nt) {
            int cc = colBase + warpCol * 32 + nt * 8 + (lane & 3) * 2;
            float b0 = bias[cc], b1 = bias[cc + 1];
            float v0 = acc[mt][nt][0] + b0;
            float v1 = acc[mt][nt][1] + b1;
            float v2 = acc[mt][nt][2] + b0;
            float v3 = acc[mt][nt][3] + b1;
            if (act) {
                v0 = (v0 > 0.f) ? v0 + 1.f : __expf(v0);
                v1 = (v1 > 0.f) ? v1 + 1.f : __expf(v1);
                v2 = (v2 > 0.f) ? v2 + 1.f : __expf(v2);
                v3 = (v3 > 0.f) ? v3 + 1.f : __expf(v3);
            }
            *(float2*)&O[(size_t)r0 * D + cc] = make_float2(v0, v1);
            *(float2*)&O[(size_t)(r0 + 8) * D + cc] = make_float2(v2, v3);
        }
    }
}

// ---------------- per-chunk local sums: KV_local[d][m], ksum_local[d] ----------------
__global__ void __launch_bounds__(256) chunk_sum_kernel()
{
    int bc = blockIdx.x;            // b*NC + c
    int h = blockIdx.y;
    int b = bc / NC, c = bc % NC;
    extern __shared__ __align__(16) float smf[];
    float* ks = smf;                 // [CHUNK][HD]
    float* vs = smf + CHUNK * HD;    // [CHUNK][HD]

    int tid = threadIdx.x;
    size_t nbase = (size_t)b * TSEQ + (size_t)c * CHUNK;

#pragma unroll
    for (int it = 0; it < 8; it++) {
        int lin = tid + it * 256;   // float4 index, 2048 total
        int t = lin >> 4;
        int d4 = lin & 15;
        size_t g = (nbase + t) * D + h * HD + d4 * 4;
        ((float4*)ks)[t * 16 + d4] = *(const float4*)&g_k[g];
        ((float4*)vs)[t * 16 + d4] = *(const float4*)&g_v[g];
    }
    __syncthreads();

    int d0 = (tid >> 4) * 4;
    int m0 = (tid & 15) * 4;
    float acc[4][4];
#pragma unroll
    for (int i = 0; i < 4; i++)
#pragma unroll
        for (int j = 0; j < 4; j++) acc[i][j] = 0.f;

#pragma unroll 4
    for (int t = 0; t < CHUNK; t++) {
        float4 kd = *(const float4*)&ks[t * HD + d0];
        float4 vm = *(const float4*)&vs[t * HD + m0];
        float ka[4] = {kd.x, kd.y, kd.z, kd.w};
        float va[4] = {vm.x, vm.y, vm.z, vm.w};
#pragma unroll
        for (int i = 0; i < 4; i++)
#pragma unroll
            for (int j = 0; j < 4; j++) acc[i][j] += ka[i] * va[j];
    }

    size_t sidx = ((size_t)(b * HEADS + h) * NC + c);
    float* ckv = g_ckv + sidx * HD * HD;
#pragma unroll
    for (int i = 0; i < 4; i++)
#pragma unroll
        for (int j = 0; j < 4; j++) ckv[(d0 + i) * HD + m0 + j] = acc[i][j];

    if (tid < HD) {
        float s = 0.f;
        for (int t = 0; t < CHUNK; t++) s += ks[t * HD + tid];
        g_cks[sidx * HD + tid] = s;
    }
}

// ---------------- exclusive prefix over chunks per (b,h) ----------------
__global__ void __launch_bounds__(256) prefix_kernel()
{
    int bh = blockIdx.x;
    int tid = threadIdx.x;
    float* base = g_ckv + (size_t)bh * NC * HD * HD;
    for (int e = tid; e < HD * HD; e += 256) {
        float carry = 0.f;
#pragma unroll
        for (int c = 0; c < NC; c++) {
            float tv = base[c * HD * HD + e];
            base[c * HD * HD + e] = carry;
            carry += tv;
        }
    }
    if (tid < HD) {
        float* kb = g_cks + (size_t)bh * NC * HD;
        float carry = 0.f;
#pragma unroll
        for (int c = 0; c < NC; c++) {
            float tv = kb[c * HD + tid];
            kb[c * HD + tid] = carry;
            carry += tv;
        }
    }
}

// ---------------- per-chunk attention ----------------
// S = mask(Q Kt), O = S V + Q KVp, denom = rowsum(S) + Q . ksum
#define QP 132
#define VP 68
#define QT_OFF 0
#define KT_OFF (HD * QP)                 // 8448
#define V_OFF  (KT_OFF + HD * QP)        // 16896
#define S_OFF  (V_OFF + CHUNK * VP)      // 25600
#define KVP_OFF (S_OFF + CHUNK * QP)     // 42496
#define KS_OFF (KVP_OFF + HD * VP)       // 46848
#define DN_OFF (KS_OFF + HD)             // 46912
#define SM2C_FLOATS (DN_OFF + CHUNK)     // 47040 floats = 188160 B

__global__ void __launch_bounds__(256) attn_chunk_kernel()
{
    int bc = blockIdx.x;
    int h = blockIdx.y;
    int b = bc / NC, c = bc % NC;
    extern __shared__ __align__(16) float smf[];
    float* Qt = smf + QT_OFF;     // [HD][QP]  (transposed: [d][i])
    float* Kt = smf + KT_OFF;     // [HD][QP]
    float* V  = smf + V_OFF;      // [CHUNK][VP]
    float* S  = smf + S_OFF;      // [CHUNK][QP] row-major [i][j]
    float* KVp = smf + KVP_OFF;   // [HD][VP]
    float* ksum = smf + KS_OFF;   // [HD]
    float* dn = smf + DN_OFF;     // [CHUNK]

    int tid = threadIdx.x;
    int tx = tid & 15, ty = tid >> 4;
    size_t nbase = (size_t)b * TSEQ + (size_t)c * CHUNK;
    size_t sidx = ((size_t)(b * HEADS + h) * NC + c);

    // loads (coalesced global, transposed store for Q/K)
#pragma unroll
    for (int it = 0; it < 32; it++) {
        int lin = tid + it * 256;    // 8192
        int i = lin >> 6, d = lin & 63;
        size_t g = (nbase + i) * D + h * HD + d;
        Qt[d * QP + i] = g_q[g];
        Kt[d * QP + i] = g_k[g];
    }
#pragma unroll
    for (int it = 0; it < 8; it++) {
        int lin = tid + it * 256;    // float4, 2048
        int i = lin >> 4, d4 = lin & 15;
        *(float4*)&V[i * VP + d4 * 4] =
            *(const float4*)&g_v[(nbase + i) * D + h * HD + d4 * 4];
    }
#pragma unroll
    for (int it = 0; it < 16; it++) {
        int lin = tid + it * 256;    // 4096
        int dd = lin >> 6, m = lin & 63;
        KVp[dd * VP + m] = g_ckv[sidx * HD * HD + lin];
    }
    if (tid < HD) ksum[tid] = g_cks[sidx * HD + tid];
    __syncthreads();

    // ---- stage 1: S = mask(Q K^T) ----
    {
        int i0 = ty * 8, j0 = tx * 8;
        float s[8][8];
#pragma unroll
        for (int i = 0; i < 8; i++)
#pragma unroll
            for (int j = 0; j < 8; j++) s[i][j] = 0.f;

#pragma unroll 8
        for (int d = 0; d < HD; d++) {
            float4 q0 = *(const float4*)&Qt[d * QP + i0];
            float4 q1 = *(const float4*)&Qt[d * QP + i0 + 4];
            float4 k0 = *(const float4*)&Kt[d * QP + j0];
            float4 k1 = *(const float4*)&Kt[d * QP + j0 + 4];
            float qa[8] = {q0.x, q0.y, q0.z, q0.w, q1.x, q1.y, q1.z, q1.w};
            float kb[8] = {k0.x, k0.y, k0.z, k0.w, k1.x, k1.y, k1.z, k1.w};
#pragma unroll
            for (int i = 0; i < 8; i++)
#pragma unroll
                for (int j = 0; j < 8; j++) s[i][j] += qa[i] * kb[j];
        }
        // causal mask (local since same chunk) + vectorized row-major store
#pragma unroll
        for (int ii = 0; ii < 8; ii++) {
            int i = i0 + ii;
            float4 o0, o1;
            o0.x = (j0 + 0 <= i) ? s[ii][0] : 0.f;
            o0.y = (j0 + 1 <= i) ? s[ii][1] : 0.f;
            o0.z = (j0 + 2 <= i) ? s[ii][2] : 0.f;
            o0.w = (j0 + 3 <= i) ? s[ii][3] : 0.f;
            o1.x = (j0 + 4 <= i) ? s[ii][4] : 0.f;
            o1.y = (j0 + 5 <= i) ? s[ii][5] : 0.f;
            o1.z = (j0 + 6 <= i) ? s[ii][6] : 0.f;
            o1.w = (j0 + 7 <= i) ? s[ii][7] : 0.f;
            *(float4*)&S[i * QP + j0] = o0;
            *(float4*)&S[i * QP + j0 + 4] = o1;
        }
    }
    __syncthreads();

    // ---- stage 2: O = S V + Q KVp ; denom ; split-store for O-proj ----
    {
        int i0 = ty * 8, m0 = tx * 4;
        float acc[8][4];
        float rs[8];
#pragma unroll
        for (int i = 0; i < 8; i++) {
            rs[i] = 0.f;
#pragma unroll
            for (int j = 0; j < 4; j++) acc[i][j] = 0.f;
        }

#pragma unroll 4
        for (int j = 0; j < CHUNK; j++) {
            float4 vv = *(const float4*)&V[j * VP + m0];
            float va[4] = {vv.x, vv.y, vv.z, vv.w};
#pragma unroll
            for (int ii = 0; ii < 8; ii++) {
                float sv = S[(i0 + ii) * QP + j];
                rs[ii] += sv;
#pragma unroll
                for (int mm = 0; mm < 4; mm++) acc[ii][mm] += sv * va[mm];
            }
        }
#pragma unroll 4
        for (int d = 0; d < HD; d++) {
            float4 q0 = *(const float4*)&Qt[d * QP + i0];
            float4 q1 = *(const float4*)&Qt[d * QP + i0 + 4];
            float qa[8] = {q0.x, q0.y, q0.z, q0.w, q1.x, q1.y, q1.z, q1.w};
            float4 kv = *(const float4*)&KVp[d * VP + m0];
            float ka[4] = {kv.x, kv.y, kv.z, kv.w};
            float kss = ksum[d];
#pragma unroll
            for (int ii = 0; ii < 8; ii++) {
                rs[ii] += qa[ii] * kss;
#pragma unroll
                for (int mm = 0; mm < 4; mm++) acc[ii][mm] += qa[ii] * ka[mm];
            }
        }
        if (tx == 0) {
#pragma unroll
            for (int ii = 0; ii < 8; ii++) dn[i0 + ii] = rs[ii];
        }
        __syncthreads();
#pragma unroll
        for (int ii = 0; ii < 8; ii++) {
            float inv = 1.f / fmaxf(dn[i0 + ii], 1e-6f);
            size_t g = (nbase + i0 + ii) * D + h * HD + m0;
            uint16_t hh[4], ll[4];
#pragma unroll
            for (int mm = 0; mm < 4; mm++)
                split2(acc[ii][mm] * inv, hh[mm], ll[mm]);
            *(uint2*)&g_phi[g] = make_uint2((uint32_t)hh[0] | ((uint32_t)hh[1] << 16),
                                            (uint32_t)hh[2] | ((uint32_t)hh[3] << 16));
            *(uint2*)&g_plo[g] = make_uint2((uint32_t)ll[0] | ((uint32_t)ll[1] << 16),
                                            (uint32_t)ll[2] | ((uint32_t)ll[3] << 16));
        }
    }
}

// ---------------- launch ----------------
extern "C" void kernel_launch(void* const* d_in, const int* in_sizes, int n_in,
                              void* d_out, int out_size)
{
    const float* x  = (const float*)d_in[0];
    const float* Wq = (const float*)d_in[1];
    const float* bq = (const float*)d_in[2];
    const float* Wk = (const float*)d_in[3];
    const float* bk = (const float*)d_in[4];
    const float* Wv = (const float*)d_in[5];
    const float* bv = (const float*)d_in[6];
    const float* Wo = (const float*)d_in[7];
    const float* bo = (const float*)d_in[8];

    int N = in_sizes[0] / D;     // b * t
    int B = N / TSEQ;
    int rowTiles = N / 128;

    cudaFuncSetAttribute(mma_gemm,
                         cudaFuncAttributeMaxDynamicSharedMemorySize, GEMM_SMEM);
    cudaFuncSetAttribute(chunk_sum_kernel,
                         cudaFuncAttributeMaxDynamicSharedMemorySize,
                         2 * CHUNK * HD * (int)sizeof(float));
    cudaFuncSetAttribute(attn_chunk_kernel,
                         cudaFuncAttributeMaxDynamicSharedMemorySize,
                         SM2C_FLOATS * (int)sizeof(float));

    // split conversions: weights + x
    convert_w<<<(4 * D * D / 4) / 256, 256>>>(Wq, Wk, Wv, Wo);
    convert_x<<<(N * D / 4 + 255) / 256, 256>>>(x, N * D / 4);

    // fused QKV projection (z = 0,1,2 -> q,k,v); elu+1 on q,k
    dim3 gq(D / 128, rowTiles, 3);
    mma_gemm<<<gq, 256, GEMM_SMEM>>>(0, 0, 0, bq, bk, bv, nullptr, 0x3);

    chunk_sum_kernel<<<dim3(B * NC, HEADS), 256,
                       2 * CHUNK * HD * sizeof(float)>>>();
    prefix_kernel<<<B * HEADS, 256>>>();
    attn_chunk_kernel<<<dim3(B * NC, HEADS), 256,
                        SM2C_FLOATS * sizeof(float)>>>();

    // output projection from split attention output -> d_out
    dim3 go(D / 128, rowTiles, 1);
    mma_gemm<<<go, 256, GEMM_SMEM>>>(1, 3, 3, bo, bo, bo, (float*)d_out, 0x0);
}

// round 7
// speedup vs baseline: 3.1586x; 1.0599x over previous
#include <cuda_runtime.h>
#include <cuda_bf16.h>
#include <cstdint>

#define D 512
#define HEADS 8
#define HD 64
#define TSEQ 1024
#define CHUNK 64
#define NC (TSEQ / CHUNK)   // 16
#define MAXB 4

// ---------------- scratch (no allocations allowed) ----------------
__device__ float g_q[MAXB * TSEQ * D];
__device__ float g_k[MAXB * TSEQ * D];
__device__ float g_v[MAXB * TSEQ * D];
__device__ float g_ckv[MAXB * HEADS * NC * HD * HD];
__device__ float g_cks[MAXB * HEADS * NC * HD];
// bf16 split operands
__device__ __nv_bfloat16 g_whi[4 * D * D];
__device__ __nv_bfloat16 g_wlo[4 * D * D];
__device__ __nv_bfloat16 g_xhi[MAXB * TSEQ * D];
__device__ __nv_bfloat16 g_xlo[MAXB * TSEQ * D];
__device__ __nv_bfloat16 g_phi[MAXB * TSEQ * D];   // post-attention activations
__device__ __nv_bfloat16 g_plo[MAXB * TSEQ * D];

// ---------------- helpers ----------------
__device__ __forceinline__ void split2(float f, uint16_t& h, uint16_t& l) {
    __nv_bfloat16 hb = __float2bfloat16_rn(f);
    float hf = __bfloat162float(hb);
    __nv_bfloat16 lb = __float2bfloat16_rn(f - hf);
    h = __bfloat16_as_ushort(hb);
    l = __bfloat16_as_ushort(lb);
}

__device__ __forceinline__ void mma_bf16(float* d, const uint32_t* a, const uint32_t* b) {
    asm volatile(
        "mma.sync.aligned.m16n8k16.row.col.f32.bf16.bf16.f32 "
        "{%0,%1,%2,%3}, {%4,%5,%6,%7}, {%8,%9}, {%0,%1,%2,%3};"
        : "+f"(d[0]), "+f"(d[1]), "+f"(d[2]), "+f"(d[3])
        : "r"(a[0]), "r"(a[1]), "r"(a[2]), "r"(a[3]), "r"(b[0]), "r"(b[1]));
}

// ---------------- conversion kernels ----------------
__global__ void __launch_bounds__(256) convert_w(
    const float* __restrict__ Wq, const float* __restrict__ Wk,
    const float* __restrict__ Wv, const float* __restrict__ Wo)
{
    int e4 = blockIdx.x * 256 + threadIdx.x;       // 0..262143 (4 * 65536)
    int w = e4 >> 16;
    int off = e4 & 65535;
    const float* src = (w == 0) ? Wq : (w == 1) ? Wk : (w == 2) ? Wv : Wo;
    float4 v = ((const float4*)src)[off];
    float f[4] = {v.x, v.y, v.z, v.w};
    uint16_t h[4], l[4];
#pragma unroll
    for (int j = 0; j < 4; ++j) split2(f[j], h[j], l[j]);
    ((uint2*)(g_whi + (size_t)w * D * D))[off] =
        make_uint2((uint32_t)h[0] | ((uint32_t)h[1] << 16),
                   (uint32_t)h[2] | ((uint32_t)h[3] << 16));
    ((uint2*)(g_wlo + (size_t)w * D * D))[off] =
        make_uint2((uint32_t)l[0] | ((uint32_t)l[1] << 16),
                   (uint32_t)l[2] | ((uint32_t)l[3] << 16));
}

__global__ void __launch_bounds__(256) convert_x(const float* __restrict__ src, int n4)
{
    int i = blockIdx.x * 256 + threadIdx.x;
    if (i >= n4) return;
    float4 v = ((const float4*)src)[i];
    float f[4] = {v.x, v.y, v.z, v.w};
    uint16_t h[4], l[4];
#pragma unroll
    for (int j = 0; j < 4; ++j) split2(f[j], h[j], l[j]);
    ((uint2*)g_xhi)[i] = make_uint2((uint32_t)h[0] | ((uint32_t)h[1] << 16),
                                    (uint32_t)h[2] | ((uint32_t)h[3] << 16));
    ((uint2*)g_xlo)[i] = make_uint2((uint32_t)l[0] | ((uint32_t)l[1] << 16),
                                    (uint32_t)l[2] | ((uint32_t)l[3] << 16));
}

// ---------------- mma.sync split-bf16 GEMM (UNCHANGED from R6 win) ----------------
#define ROWU 36
#define ARRU (128 * ROWU)      // 4608
#define BUFU (4 * ARRU)        // 18432
#define GEMM_SMEM (2 * BUFU * 4)   // 147456 bytes

__device__ __forceinline__ void load_chunk(
    uint32_t* dst, const uint32_t* Ahi, const uint32_t* Alo,
    const uint32_t* Bhi, const uint32_t* Blo,
    int rowBase, int colBase, int k0u, int tid)
{
#pragma unroll
    for (int it = 0; it < 4; ++it) {
        int lin = tid + it * 256;
        int r = lin >> 3, q = lin & 7;
        uint4 v = *(const uint4*)(Ahi + (size_t)(rowBase + r) * 256 + k0u + q * 4);
        *(uint4*)(dst + r * ROWU + q * 4) = v;
    }
#pragma unroll
    for (int it = 0; it < 4; ++it) {
        int lin = tid + it * 256;
        int r = lin >> 3, q = lin & 7;
        uint4 v = *(const uint4*)(Alo + (size_t)(rowBase + r) * 256 + k0u + q * 4);
        *(uint4*)(dst + ARRU + r * ROWU + q * 4) = v;
    }
#pragma unroll
    for (int it = 0; it < 4; ++it) {
        int lin = tid + it * 256;
        int r = lin >> 3, q = lin & 7;
        uint4 v = *(const uint4*)(Bhi + (size_t)(colBase + r) * 256 + k0u + q * 4);
        *(uint4*)(dst + 2 * ARRU + r * ROWU + q * 4) = v;
    }
#pragma unroll
    for (int it = 0; it < 4; ++it) {
        int lin = tid + it * 256;
        int r = lin >> 3, q = lin & 7;
        uint4 v = *(const uint4*)(Blo + (size_t)(colBase + r) * 256 + k0u + q * 4);
        *(uint4*)(dst + 3 * ARRU + r * ROWU + q * 4) = v;
    }
}

__global__ void __launch_bounds__(256, 1) mma_gemm(
    int asel, int wBase, int oselBase,
    const float* __restrict__ bias0, const float* __restrict__ bias1,
    const float* __restrict__ bias2,
    float* __restrict__ Oext, int actmask)
{
    extern __shared__ __align__(16) uint32_t smu[];
    int tid = threadIdx.x, lane = tid & 31, wid = tid >> 5;
    int warpRow = wid >> 2;
    int warpCol = wid & 3;
    int z = blockIdx.z;
    int rowBase = blockIdx.y * 128;
    int colBase = blockIdx.x * 128;

    const uint32_t* Ahi = asel ? (const uint32_t*)g_phi : (const uint32_t*)g_xhi;
    const uint32_t* Alo = asel ? (const uint32_t*)g_plo : (const uint32_t*)g_xlo;
    int wz = wBase + z;
    const uint32_t* Bhi = (const uint32_t*)g_whi + (size_t)wz * (D * D / 2);
    const uint32_t* Blo = (const uint32_t*)g_wlo + (size_t)wz * (D * D / 2);
    const float* bias = (z == 0) ? bias0 : (z == 1) ? bias1 : bias2;
    int osel = oselBase + z;
    float* O = (osel == 3) ? Oext : (osel == 0 ? g_q : (osel == 1 ? g_k : g_v));
    int act = (actmask >> z) & 1;

    float acc[4][4][4];
#pragma unroll
    for (int mt = 0; mt < 4; ++mt)
#pragma unroll
        for (int nt = 0; nt < 4; ++nt)
#pragma unroll
            for (int r = 0; r < 4; ++r) acc[mt][nt][r] = 0.f;

    load_chunk(smu, Ahi, Alo, Bhi, Blo, rowBase, colBase, 0, tid);
    __syncthreads();

    for (int c = 0; c < 8; ++c) {
        int buf = c & 1;
        if (c < 7)
            load_chunk(smu + ((c + 1) & 1) * BUFU, Ahi, Alo, Bhi, Blo,
                       rowBase, colBase, (c + 1) * 32, tid);

        const uint32_t* AH = smu + buf * BUFU;
        const uint32_t* AL = AH + ARRU;
        const uint32_t* BH = AH + 2 * ARRU;
        const uint32_t* BL = AH + 3 * ARRU;
#pragma unroll
        for (int ks = 0; ks < 4; ++ks) {
            int kpb = ks * 8 + (lane & 3);
            uint32_t ahi[4][4], alo[4][4], bhi[4][2], blo[4][2];
#pragma unroll
            for (int mt = 0; mt < 4; ++mt) {
                int r0 = (warpRow * 64 + mt * 16 + (lane >> 2)) * ROWU;
                ahi[mt][0] = AH[r0 + kpb];
                ahi[mt][1] = AH[r0 + 8 * ROWU + kpb];
                ahi[mt][2] = AH[r0 + kpb + 4];
                ahi[mt][3] = AH[r0 + 8 * ROWU + kpb + 4];
                alo[mt][0] = AL[r0 + kpb];
                alo[mt][1] = AL[r0 + 8 * ROWU + kpb];
                alo[mt][2] = AL[r0 + kpb + 4];
                alo[mt][3] = AL[r0 + 8 * ROWU + kpb + 4];
            }
#pragma unroll
            for (int nt = 0; nt < 4; ++nt) {
                int n0 = (warpCol * 32 + nt * 8 + (lane >> 2)) * ROWU;
                bhi[nt][0] = BH[n0 + kpb];
                bhi[nt][1] = BH[n0 + kpb + 4];
                blo[nt][0] = BL[n0 + kpb];
                blo[nt][1] = BL[n0 + kpb + 4];
            }
#pragma unroll
            for (int mt = 0; mt < 4; ++mt)
#pragma unroll
                for (int nt = 0; nt < 4; ++nt) {
                    mma_bf16(acc[mt][nt], ahi[mt], bhi[nt]);
                    mma_bf16(acc[mt][nt], ahi[mt], blo[nt]);
                    mma_bf16(acc[mt][nt], alo[mt], bhi[nt]);
                }
        }
        __syncthreads();
    }

#pragma unroll
    for (int mt = 0; mt < 4; ++mt) {
        int r0 = rowBase + warpRow * 64 + mt * 16 + (lane >> 2);
#pragma unroll
        for (int nt = 0; nt < 4; ++nt) {
            int cc = colBase + warpCol * 32 + nt * 8 + (lane & 3) * 2;
            float b0 = bias[cc], b1 = bias[cc + 1];
            float v0 = acc[mt][nt][0] + b0;
            float v1 = acc[mt][nt][1] + b1;
            float v2 = acc[mt][nt][2] + b0;
            float v3 = acc[mt][nt][3] + b1;
            if (act) {
                v0 = (v0 > 0.f) ? v0 + 1.f : __expf(v0);
                v1 = (v1 > 0.f) ? v1 + 1.f : __expf(v1);
                v2 = (v2 > 0.f) ? v2 + 1.f : __expf(v2);
                v3 = (v3 > 0.f) ? v3 + 1.f : __expf(v3);
            }
            *(float2*)&O[(size_t)r0 * D + cc] = make_float2(v0, v1);
            *(float2*)&O[(size_t)(r0 + 8) * D + cc] = make_float2(v2, v3);
        }
    }
}

// ---------------- per-chunk local sums (CHUNK=64) ----------------
// grid (B*NC, HEADS), 256 threads; thread (d0,m0) computes 4x4 of KV[64][64].
__global__ void __launch_bounds__(256) chunk_sum_kernel()
{
    int bc = blockIdx.x;            // b*NC + c
    int h = blockIdx.y;
    int b = bc / NC, c = bc % NC;
    extern __shared__ __align__(16) float smf[];
    float* ks = smf;                   // [CHUNK][HD]
    float* vs = smf + CHUNK * HD;      // [CHUNK][HD]

    int tid = threadIdx.x;
    size_t nbase = (size_t)b * TSEQ + (size_t)c * CHUNK;

#pragma unroll
    for (int it = 0; it < 4; it++) {
        int lin = tid + it * 256;   // float4 index, 1024 total
        int t = lin >> 4;
        int d4 = lin & 15;
        size_t g = (nbase + t) * D + h * HD + d4 * 4;
        ((float4*)ks)[t * 16 + d4] = *(const float4*)&g_k[g];
        ((float4*)vs)[t * 16 + d4] = *(const float4*)&g_v[g];
    }
    __syncthreads();

    int d0 = (tid >> 4) * 4;
    int m0 = (tid & 15) * 4;
    float acc[4][4];
#pragma unroll
    for (int i = 0; i < 4; i++)
#pragma unroll
        for (int j = 0; j < 4; j++) acc[i][j] = 0.f;

#pragma unroll 4
    for (int t = 0; t < CHUNK; t++) {
        float4 kd = *(const float4*)&ks[t * HD + d0];
        float4 vm = *(const float4*)&vs[t * HD + m0];
        float ka[4] = {kd.x, kd.y, kd.z, kd.w};
        float va[4] = {vm.x, vm.y, vm.z, vm.w};
#pragma unroll
        for (int i = 0; i < 4; i++)
#pragma unroll
            for (int j = 0; j < 4; j++) acc[i][j] += ka[i] * va[j];
    }

    size_t sidx = ((size_t)(b * HEADS + h) * NC + c);
    float* ckv = g_ckv + sidx * HD * HD;
#pragma unroll
    for (int i = 0; i < 4; i++)
#pragma unroll
        for (int j = 0; j < 4; j++) ckv[(d0 + i) * HD + m0 + j] = acc[i][j];

    if (tid < HD) {
        float s = 0.f;
#pragma unroll 4
        for (int t = 0; t < CHUNK; t++) s += ks[t * HD + tid];
        g_cks[sidx * HD + tid] = s;
    }
}

// ---------------- exclusive prefix over chunks per (b,h) ----------------
__global__ void __launch_bounds__(256) prefix_kernel()
{
    int bh = blockIdx.x;
    int tid = threadIdx.x;
    float* base = g_ckv + (size_t)bh * NC * HD * HD;
    for (int e = tid; e < HD * HD; e += 256) {
        float carry = 0.f;
#pragma unroll
        for (int c = 0; c < NC; c++) {
            float tv = base[c * HD * HD + e];
            base[c * HD * HD + e] = carry;
            carry += tv;
        }
    }
    if (tid < HD) {
        float* kb = g_cks + (size_t)bh * NC * HD;
        float carry = 0.f;
#pragma unroll
        for (int c = 0; c < NC; c++) {
            float tv = kb[c * HD + tid];
            kb[c * HD + tid] = carry;
            carry += tv;
        }
    }
}

// ---------------- per-chunk attention (CHUNK=64) ----------------
// S = mask(Q Kt), O = S V + Q KVp, denom = rowsum(S) + Q . ksum
// smem rows stride 68 floats; total 21888 floats = 87552 B -> 2 CTAs/SM.
#define SP 68
#define QT_OFF 0
#define KT_OFF (HD * SP)                 // 4352
#define V_OFF  (KT_OFF + HD * SP)        // 8704
#define S_OFF  (V_OFF + CHUNK * SP)      // 13056
#define KVP_OFF (S_OFF + CHUNK * SP)     // 17408
#define KS_OFF (KVP_OFF + HD * SP)       // 21760
#define DN_OFF (KS_OFF + HD)             // 21824
#define SM2C_FLOATS (DN_OFF + CHUNK)     // 21888 floats = 87552 B

__global__ void __launch_bounds__(256) attn_chunk_kernel()
{
    int bc = blockIdx.x;
    int h = blockIdx.y;
    int b = bc / NC, c = bc % NC;
    extern __shared__ __align__(16) float smf[];
    float* Qt = smf + QT_OFF;     // [HD][SP]  (transposed: [d][i])
    float* Kt = smf + KT_OFF;     // [HD][SP]
    float* V  = smf + V_OFF;      // [CHUNK][SP]
    float* S  = smf + S_OFF;      // [CHUNK][SP] row-major [i][j]
    float* KVp = smf + KVP_OFF;   // [HD][SP]
    float* ksum = smf + KS_OFF;   // [HD]
    float* dn = smf + DN_OFF;     // [CHUNK]

    int tid = threadIdx.x;
    int tx = tid & 15, ty = tid >> 4;
    size_t nbase = (size_t)b * TSEQ + (size_t)c * CHUNK;
    size_t sidx = ((size_t)(b * HEADS + h) * NC + c);

    // loads (coalesced global, transposed store for Q/K)
#pragma unroll
    for (int it = 0; it < 16; it++) {
        int lin = tid + it * 256;    // 4096
        int i = lin >> 6, d = lin & 63;
        size_t g = (nbase + i) * D + h * HD + d;
        Qt[d * SP + i] = g_q[g];
        Kt[d * SP + i] = g_k[g];
    }
#pragma unroll
    for (int it = 0; it < 4; it++) {
        int lin = tid + it * 256;    // float4, 1024
        int i = lin >> 4, d4 = lin & 15;
        *(float4*)&V[i * SP + d4 * 4] =
            *(const float4*)&g_v[(nbase + i) * D + h * HD + d4 * 4];
    }
#pragma unroll
    for (int it = 0; it < 4; it++) {
        int lin = tid + it * 256;    // float4, 1024
        int dd = lin >> 4, m4 = lin & 15;
        *(float4*)&KVp[dd * SP + m4 * 4] =
            *(const float4*)&g_ckv[sidx * HD * HD + lin * 4];
    }
    if (tid < HD) ksum[tid] = g_cks[sidx * HD + tid];
    __syncthreads();

    // ---- stage 1: S = mask(Q K^T), 4x4 tile per thread ----
    {
        int i0 = ty * 4, j0 = tx * 4;
        float s[4][4];
#pragma unroll
        for (int i = 0; i < 4; i++)
#pragma unroll
            for (int j = 0; j < 4; j++) s[i][j] = 0.f;

#pragma unroll 8
        for (int d = 0; d < HD; d++) {
            float4 q0 = *(const float4*)&Qt[d * SP + i0];
            float4 k0 = *(const float4*)&Kt[d * SP + j0];
            float qa[4] = {q0.x, q0.y, q0.z, q0.w};
            float kb[4] = {k0.x, k0.y, k0.z, k0.w};
#pragma unroll
            for (int i = 0; i < 4; i++)
#pragma unroll
                for (int j = 0; j < 4; j++) s[i][j] += qa[i] * kb[j];
        }
#pragma unroll
        for (int ii = 0; ii < 4; ii++) {
            int i = i0 + ii;
            float4 o0;
            o0.x = (j0 + 0 <= i) ? s[ii][0] : 0.f;
            o0.y = (j0 + 1 <= i) ? s[ii][1] : 0.f;
            o0.z = (j0 + 2 <= i) ? s[ii][2] : 0.f;
            o0.w = (j0 + 3 <= i) ? s[ii][3] : 0.f;
            *(float4*)&S[i * SP + j0] = o0;
        }
    }
    __syncthreads();

    // ---- stage 2: O = S V + Q KVp ; denom ; split-store for O-proj ----
    {
        int i0 = ty * 4, m0 = tx * 4;
        float acc[4][4];
        float rs[4];
#pragma unroll
        for (int i = 0; i < 4; i++) {
            rs[i] = 0.f;
#pragma unroll
            for (int j = 0; j < 4; j++) acc[i][j] = 0.f;
        }

#pragma unroll 4
        for (int j = 0; j < CHUNK; j++) {
            float4 vv = *(const float4*)&V[j * SP + m0];
            float va[4] = {vv.x, vv.y, vv.z, vv.w};
#pragma unroll
            for (int ii = 0; ii < 4; ii++) {
                float sv = S[(i0 + ii) * SP + j];
                rs[ii] += sv;
#pragma unroll
                for (int mm = 0; mm < 4; mm++) acc[ii][mm] += sv * va[mm];
            }
        }
#pragma unroll 4
        for (int d = 0; d < HD; d++) {
            float4 q0 = *(const float4*)&Qt[d * SP + i0];
            float qa[4] = {q0.x, q0.y, q0.z, q0.w};
            float4 kv = *(const float4*)&KVp[d * SP + m0];
            float ka[4] = {kv.x, kv.y, kv.z, kv.w};
            float kss = ksum[d];
#pragma unroll
            for (int ii = 0; ii < 4; ii++) {
                rs[ii] += qa[ii] * kss;
#pragma unroll
                for (int mm = 0; mm < 4; mm++) acc[ii][mm] += qa[ii] * ka[mm];
            }
        }
        if (tx == 0) {
#pragma unroll
            for (int ii = 0; ii < 4; ii++) dn[i0 + ii] = rs[ii];
        }
        __syncthreads();
#pragma unroll
        for (int ii = 0; ii < 4; ii++) {
            float inv = 1.f / fmaxf(dn[i0 + ii], 1e-6f);
            size_t g = (nbase + i0 + ii) * D + h * HD + m0;
            uint16_t hh[4], ll[4];
#pragma unroll
            for (int mm = 0; mm < 4; mm++)
                split2(acc[ii][mm] * inv, hh[mm], ll[mm]);
            *(uint2*)&g_phi[g] = make_uint2((uint32_t)hh[0] | ((uint32_t)hh[1] << 16),
                                            (uint32_t)hh[2] | ((uint32_t)hh[3] << 16));
            *(uint2*)&g_plo[g] = make_uint2((uint32_t)ll[0] | ((uint32_t)ll[1] << 16),
                                            (uint32_t)ll[2] | ((uint32_t)ll[3] << 16));
        }
    }
}

// ---------------- launch ----------------
extern "C" void kernel_launch(void* const* d_in, const int* in_sizes, int n_in,
                              void* d_out, int out_size)
{
    const float* x  = (const float*)d_in[0];
    const float* Wq = (const float*)d_in[1];
    const float* bq = (const float*)d_in[2];
    const float* Wk = (const float*)d_in[3];
    const float* bk = (const float*)d_in[4];
    const float* Wv = (const float*)d_in[5];
    const float* bv = (const float*)d_in[6];
    const float* Wo = (const float*)d_in[7];
    const float* bo = (const float*)d_in[8];

    int N = in_sizes[0] / D;     // b * t
    int B = N / TSEQ;
    int rowTiles = N / 128;

    cudaFuncSetAttribute(mma_gemm,
                         cudaFuncAttributeMaxDynamicSharedMemorySize, GEMM_SMEM);
    cudaFuncSetAttribute(chunk_sum_kernel,
                         cudaFuncAttributeMaxDynamicSharedMemorySize,
                         2 * CHUNK * HD * (int)sizeof(float));
    cudaFuncSetAttribute(attn_chunk_kernel,
                         cudaFuncAttributeMaxDynamicSharedMemorySize,
                         SM2C_FLOATS * (int)sizeof(float));

    // split conversions: weights + x
    convert_w<<<(4 * D * D / 4) / 256, 256>>>(Wq, Wk, Wv, Wo);
    convert_x<<<(N * D / 4 + 255) / 256, 256>>>(x, N * D / 4);

    // fused QKV projection (z = 0,1,2 -> q,k,v); elu+1 on q,k
    dim3 gq(D / 128, rowTiles, 3);
    mma_gemm<<<gq, 256, GEMM_SMEM>>>(0, 0, 0, bq, bk, bv, nullptr, 0x3);

    chunk_sum_kernel<<<dim3(B * NC, HEADS), 256,
                       2 * CHUNK * HD * sizeof(float)>>>();
    prefix_kernel<<<B * HEADS, 256>>>();
    attn_chunk_kernel<<<dim3(B * NC, HEADS), 256,
                        SM2C_FLOATS * sizeof(float)>>>();

    // output projection from split attention output -> d_out
    dim3 go(D / 128, rowTiles, 1);
    mma_gemm<<<go, 256, GEMM_SMEM>>>(1, 3, 3, bo, bo, bo, (float*)d_out, 0x0);
}

// round 8
// speedup vs baseline: 3.3094x; 1.0477x over previous
#include <cuda_runtime.h>
#include <cuda_bf16.h>
#include <cstdint>

#define D 512
#define HEADS 8
#define HD 64
#define TSEQ 1024
#define CHUNK 64
#define NC (TSEQ / CHUNK)   // 16
#define MAXB 4

// ---------------- scratch (no allocations allowed) ----------------
__device__ float g_q[MAXB * TSEQ * D];
__device__ float g_k[MAXB * TSEQ * D];
__device__ float g_v[MAXB * TSEQ * D];
__device__ float g_ckv[MAXB * HEADS * NC * HD * HD];
__device__ float g_cks[MAXB * HEADS * NC * HD];
// bf16 split operands
__device__ __nv_bfloat16 g_whi[4 * D * D];
__device__ __nv_bfloat16 g_wlo[4 * D * D];
__device__ __nv_bfloat16 g_xhi[MAXB * TSEQ * D];
__device__ __nv_bfloat16 g_xlo[MAXB * TSEQ * D];
__device__ __nv_bfloat16 g_phi[MAXB * TSEQ * D];   // post-attention activations
__device__ __nv_bfloat16 g_plo[MAXB * TSEQ * D];

// ---------------- helpers ----------------
__device__ __forceinline__ void split2(float f, uint16_t& h, uint16_t& l) {
    __nv_bfloat16 hb = __float2bfloat16_rn(f);
    float hf = __bfloat162float(hb);
    __nv_bfloat16 lb = __float2bfloat16_rn(f - hf);
    h = __bfloat16_as_ushort(hb);
    l = __bfloat16_as_ushort(lb);
}

__device__ __forceinline__ void mma_bf16(float* d, const uint32_t* a, const uint32_t* b) {
    asm volatile(
        "mma.sync.aligned.m16n8k16.row.col.f32.bf16.bf16.f32 "
        "{%0,%1,%2,%3}, {%4,%5,%6,%7}, {%8,%9}, {%0,%1,%2,%3};"
        : "+f"(d[0]), "+f"(d[1]), "+f"(d[2]), "+f"(d[3])
        : "r"(a[0]), "r"(a[1]), "r"(a[2]), "r"(a[3]), "r"(b[0]), "r"(b[1]));
}

__device__ __forceinline__ uint32_t smem_u32(const void* p) {
    uint32_t a;
    asm("{ .reg .u64 t; cvta.to.shared.u64 t, %1; cvt.u32.u64 %0, t; }"
        : "=r"(a) : "l"(p));
    return a;
}
__device__ __forceinline__ void cp16(uint32_t dst, const void* src) {
    asm volatile("cp.async.cg.shared.global [%0], [%1], 16;"
                 :: "r"(dst), "l"(src));
}
#define CP_COMMIT() asm volatile("cp.async.commit_group;" ::: "memory")
#define CP_WAIT(n)  asm volatile("cp.async.wait_group %0;" :: "n"(n) : "memory")

// ---------------- conversion kernels ----------------
__global__ void __launch_bounds__(256) convert_w(
    const float* __restrict__ Wq, const float* __restrict__ Wk,
    const float* __restrict__ Wv, const float* __restrict__ Wo)
{
    int e4 = blockIdx.x * 256 + threadIdx.x;       // 0..262143 (4 * 65536)
    int w = e4 >> 16;
    int off = e4 & 65535;
    const float* src = (w == 0) ? Wq : (w == 1) ? Wk : (w == 2) ? Wv : Wo;
    float4 v = ((const float4*)src)[off];
    float f[4] = {v.x, v.y, v.z, v.w};
    uint16_t h[4], l[4];
#pragma unroll
    for (int j = 0; j < 4; ++j) split2(f[j], h[j], l[j]);
    ((uint2*)(g_whi + (size_t)w * D * D))[off] =
        make_uint2((uint32_t)h[0] | ((uint32_t)h[1] << 16),
                   (uint32_t)h[2] | ((uint32_t)h[3] << 16));
    ((uint2*)(g_wlo + (size_t)w * D * D))[off] =
        make_uint2((uint32_t)l[0] | ((uint32_t)l[1] << 16),
                   (uint32_t)l[2] | ((uint32_t)l[3] << 16));
}

__global__ void __launch_bounds__(256) convert_x(const float* __restrict__ src, int n4)
{
    int i = blockIdx.x * 256 + threadIdx.x;
    if (i >= n4) return;
    float4 v = ((const float4*)src)[i];
    float f[4] = {v.x, v.y, v.z, v.w};
    uint16_t h[4], l[4];
#pragma unroll
    for (int j = 0; j < 4; ++j) split2(f[j], h[j], l[j]);
    ((uint2*)g_xhi)[i] = make_uint2((uint32_t)h[0] | ((uint32_t)h[1] << 16),
                                    (uint32_t)h[2] | ((uint32_t)h[3] << 16));
    ((uint2*)g_xlo)[i] = make_uint2((uint32_t)l[0] | ((uint32_t)l[1] << 16),
                                    (uint32_t)l[2] | ((uint32_t)l[3] << 16));
}

// ---------------- mma.sync split-bf16 GEMM (cp.async pipelined) ----------------
#define ROWU 36
#define ARRU (128 * ROWU)      // 4608
#define BUFU (4 * ARRU)        // 18432
#define GEMM_SMEM (2 * BUFU * 4)   // 147456 bytes

// async copy one K-chunk (A/B hi/lo) into smem buffer at byte base sbB
__device__ __forceinline__ void load_chunk_async(
    uint32_t sbB, const uint32_t* Ahi, const uint32_t* Alo,
    const uint32_t* Bhi, const uint32_t* Blo,
    int rowBase, int colBase, int k0u, int tid)
{
#pragma unroll
    for (int it = 0; it < 4; ++it) {
        int lin = tid + it * 256;          // 0..1023
        int r = lin >> 3, q = lin & 7;
        uint32_t dOff = (uint32_t)(r * ROWU + q * 4) * 4;
        cp16(sbB + dOff, Ahi + (size_t)(rowBase + r) * 256 + k0u + q * 4);
        cp16(sbB + ARRU * 4 + dOff, Alo + (size_t)(rowBase + r) * 256 + k0u + q * 4);
        cp16(sbB + 2 * ARRU * 4 + dOff, Bhi + (size_t)(colBase + r) * 256 + k0u + q * 4);
        cp16(sbB + 3 * ARRU * 4 + dOff, Blo + (size_t)(colBase + r) * 256 + k0u + q * 4);
    }
}

__global__ void __launch_bounds__(256, 1) mma_gemm(
    int asel, int wBase, int oselBase,
    const float* __restrict__ bias0, const float* __restrict__ bias1,
    const float* __restrict__ bias2,
    float* __restrict__ Oext, int actmask)
{
    extern __shared__ __align__(16) uint32_t smu[];
    int tid = threadIdx.x, lane = tid & 31, wid = tid >> 5;
    int warpRow = wid >> 2;
    int warpCol = wid & 3;
    int z = blockIdx.z;
    int rowBase = blockIdx.y * 128;
    int colBase = blockIdx.x * 128;

    const uint32_t* Ahi = asel ? (const uint32_t*)g_phi : (const uint32_t*)g_xhi;
    const uint32_t* Alo = asel ? (const uint32_t*)g_plo : (const uint32_t*)g_xlo;
    int wz = wBase + z;
    const uint32_t* Bhi = (const uint32_t*)g_whi + (size_t)wz * (D * D / 2);
    const uint32_t* Blo = (const uint32_t*)g_wlo + (size_t)wz * (D * D / 2);
    const float* bias = (z == 0) ? bias0 : (z == 1) ? bias1 : bias2;
    int osel = oselBase + z;
    float* O = (osel == 3) ? Oext : (osel == 0 ? g_q : (osel == 1 ? g_k : g_v));
    int act = (actmask >> z) & 1;

    uint32_t sbB = smem_u32(smu);

    float acc[4][4][4];
#pragma unroll
    for (int mt = 0; mt < 4; ++mt)
#pragma unroll
        for (int nt = 0; nt < 4; ++nt)
#pragma unroll
            for (int r = 0; r < 4; ++r) acc[mt][nt][r] = 0.f;

    load_chunk_async(sbB, Ahi, Alo, Bhi, Blo, rowBase, colBase, 0, tid);
    CP_COMMIT();

    for (int c = 0; c < 8; ++c) {
        int buf = c & 1;
        if (c < 7) {
            load_chunk_async(sbB + ((c + 1) & 1) * BUFU * 4,
                             Ahi, Alo, Bhi, Blo, rowBase, colBase,
                             (c + 1) * 32, tid);
            CP_COMMIT();
            CP_WAIT(1);             // chunk c complete, c+1 in flight
        } else {
            CP_WAIT(0);             // last chunk complete
        }
        __syncthreads();

        const uint32_t* AH = smu + buf * BUFU;
        const uint32_t* AL = AH + ARRU;
        const uint32_t* BH = AH + 2 * ARRU;
        const uint32_t* BL = AH + 3 * ARRU;
#pragma unroll
        for (int ks = 0; ks < 4; ++ks) {
            int kpb = ks * 8 + (lane & 3);
            uint32_t ahi[4][4], alo[4][4], bhi[4][2], blo[4][2];
#pragma unroll
            for (int mt = 0; mt < 4; ++mt) {
                int r0 = (warpRow * 64 + mt * 16 + (lane >> 2)) * ROWU;
                ahi[mt][0] = AH[r0 + kpb];
                ahi[mt][1] = AH[r0 + 8 * ROWU + kpb];
                ahi[mt][2] = AH[r0 + kpb + 4];
                ahi[mt][3] = AH[r0 + 8 * ROWU + kpb + 4];
                alo[mt][0] = AL[r0 + kpb];
                alo[mt][1] = AL[r0 + 8 * ROWU + kpb];
                alo[mt][2] = AL[r0 + kpb + 4];
                alo[mt][3] = AL[r0 + 8 * ROWU + kpb + 4];
            }
#pragma unroll
            for (int nt = 0; nt < 4; ++nt) {
                int n0 = (warpCol * 32 + nt * 8 + (lane >> 2)) * ROWU;
                bhi[nt][0] = BH[n0 + kpb];
                bhi[nt][1] = BH[n0 + kpb + 4];
                blo[nt][0] = BL[n0 + kpb];
                blo[nt][1] = BL[n0 + kpb + 4];
            }
#pragma unroll
            for (int mt = 0; mt < 4; ++mt)
#pragma unroll
                for (int nt = 0; nt < 4; ++nt) {
                    mma_bf16(acc[mt][nt], ahi[mt], bhi[nt]);
                    mma_bf16(acc[mt][nt], ahi[mt], blo[nt]);
                    mma_bf16(acc[mt][nt], alo[mt], bhi[nt]);
                }
        }
        __syncthreads();
    }

#pragma unroll
    for (int mt = 0; mt < 4; ++mt) {
        int r0 = rowBase + warpRow * 64 + mt * 16 + (lane >> 2);
#pragma unroll
        for (int nt = 0; nt < 4; ++nt) {
            int cc = colBase + warpCol * 32 + nt * 8 + (lane & 3) * 2;
            float b0 = bias[cc], b1 = bias[cc + 1];
            float v0 = acc[mt][nt][0] + b0;
            float v1 = acc[mt][nt][1] + b1;
            float v2 = acc[mt][nt][2] + b0;
            float v3 = acc[mt][nt][3] + b1;
            if (act) {
                v0 = (v0 > 0.f) ? v0 + 1.f : __expf(v0);
                v1 = (v1 > 0.f) ? v1 + 1.f : __expf(v1);
                v2 = (v2 > 0.f) ? v2 + 1.f : __expf(v2);
                v3 = (v3 > 0.f) ? v3 + 1.f : __expf(v3);
            }
            *(float2*)&O[(size_t)r0 * D + cc] = make_float2(v0, v1);
            *(float2*)&O[(size_t)(r0 + 8) * D + cc] = make_float2(v2, v3);
        }
    }
}

// ---------------- per-chunk local sums (CHUNK=64, 512 threads) ----------------
// thread (d0= (tid>>5)*4, m0=(tid&31)*2) computes 4x2 of KV[64][64].
// k-row load is a warp broadcast; v float2 load is conflict-free.
__global__ void __launch_bounds__(512) chunk_sum_kernel()
{
    int bc = blockIdx.x;            // b*NC + c
    int h = blockIdx.y;
    int b = bc / NC, c = bc % NC;
    extern __shared__ __align__(16) float smf[];
    float* ks = smf;                   // [CHUNK][HD]
    float* vs = smf + CHUNK * HD;      // [CHUNK][HD]

    int tid = threadIdx.x;
    size_t nbase = (size_t)b * TSEQ + (size_t)c * CHUNK;

#pragma unroll
    for (int it = 0; it < 2; it++) {
        int lin = tid + it * 512;   // float4 index, 1024 total
        int t = lin >> 4;
        int d4 = lin & 15;
        size_t g = (nbase + t) * D + h * HD + d4 * 4;
        ((float4*)ks)[t * 16 + d4] = *(const float4*)&g_k[g];
        ((float4*)vs)[t * 16 + d4] = *(const float4*)&g_v[g];
    }
    __syncthreads();

    int d0 = (tid >> 5) * 4;       // 0..60
    int m0 = (tid & 31) * 2;       // 0..62
    float acc[4][2];
#pragma unroll
    for (int i = 0; i < 4; i++) {
        acc[i][0] = 0.f;
        acc[i][1] = 0.f;
    }

#pragma unroll 4
    for (int t = 0; t < CHUNK; t++) {
        float4 kd = *(const float4*)&ks[t * HD + d0];
        float2 vm = *(const float2*)&vs[t * HD + m0];
        float ka[4] = {kd.x, kd.y, kd.z, kd.w};
#pragma unroll
        for (int i = 0; i < 4; i++) {
            acc[i][0] += ka[i] * vm.x;
            acc[i][1] += ka[i] * vm.y;
        }
    }

    size_t sidx = ((size_t)(b * HEADS + h) * NC + c);
    float* ckv = g_ckv + sidx * HD * HD;
#pragma unroll
    for (int i = 0; i < 4; i++)
        *(float2*)&ckv[(d0 + i) * HD + m0] = make_float2(acc[i][0], acc[i][1]);

    if (tid < HD) {
        float s = 0.f;
#pragma unroll 4
        for (int t = 0; t < CHUNK; t++) s += ks[t * HD + tid];
        g_cks[sidx * HD + tid] = s;
    }
}

// ---------------- exclusive prefix over chunks per (b,h) ----------------
__global__ void __launch_bounds__(256) prefix_kernel()
{
    int bh = blockIdx.x;
    int tid = threadIdx.x;
    float* base = g_ckv + (size_t)bh * NC * HD * HD;
    for (int e = tid; e < HD * HD; e += 256) {
        float carry = 0.f;
#pragma unroll
        for (int c = 0; c < NC; c++) {
            float tv = base[c * HD * HD + e];
            base[c * HD * HD + e] = carry;
            carry += tv;
        }
    }
    if (tid < HD) {
        float* kb = g_cks + (size_t)bh * NC * HD;
        float carry = 0.f;
#pragma unroll
        for (int c = 0; c < NC; c++) {
            float tv = kb[c * HD + tid];
            kb[c * HD + tid] = carry;
            carry += tv;
        }
    }
}

// ---------------- per-chunk attention (CHUNK=64) ----------------
// S = mask(Q Kt), O = S V + Q KVp, denom = rowsum(S) + Q . ksum
#define SP 68
#define QT_OFF 0
#define KT_OFF (HD * SP)                 // 4352
#define V_OFF  (KT_OFF + HD * SP)        // 8704
#define S_OFF  (V_OFF + CHUNK * SP)      // 13056
#define KVP_OFF (S_OFF + CHUNK * SP)     // 17408
#define KS_OFF (KVP_OFF + HD * SP)       // 21760
#define DN_OFF (KS_OFF + HD)             // 21824
#define SM2C_FLOATS (DN_OFF + CHUNK)     // 21888 floats = 87552 B

__global__ void __launch_bounds__(256) attn_chunk_kernel()
{
    int bc = blockIdx.x;
    int h = blockIdx.y;
    int b = bc / NC, c = bc % NC;
    extern __shared__ __align__(16) float smf[];
    float* Qt = smf + QT_OFF;     // [HD][SP]  (transposed: [d][i])
    float* Kt = smf + KT_OFF;     // [HD][SP]
    float* V  = smf + V_OFF;      // [CHUNK][SP]
    float* S  = smf + S_OFF;      // [CHUNK][SP] row-major [i][j]
    float* KVp = smf + KVP_OFF;   // [HD][SP]
    float* ksum = smf + KS_OFF;   // [HD]
    float* dn = smf + DN_OFF;     // [CHUNK]

    int tid = threadIdx.x;
    int tx = tid & 15, ty = tid >> 4;
    size_t nbase = (size_t)b * TSEQ + (size_t)c * CHUNK;
    size_t sidx = ((size_t)(b * HEADS + h) * NC + c);

    // loads (coalesced global, transposed store for Q/K)
#pragma unroll
    for (int it = 0; it < 16; it++) {
        int lin = tid + it * 256;    // 4096
        int i = lin >> 6, d = lin & 63;
        size_t g = (nbase + i) * D + h * HD + d;
        Qt[d * SP + i] = g_q[g];
        Kt[d * SP + i] = g_k[g];
    }
#pragma unroll
    for (int it = 0; it < 4; it++) {
        int lin = tid + it * 256;    // float4, 1024
        int i = lin >> 4, d4 = lin & 15;
        *(float4*)&V[i * SP + d4 * 4] =
            *(const float4*)&g_v[(nbase + i) * D + h * HD + d4 * 4];
    }
#pragma unroll
    for (int it = 0; it < 4; it++) {
        int lin = tid + it * 256;    // float4, 1024
        int dd = lin >> 4, m4 = lin & 15;
        *(float4*)&KVp[dd * SP + m4 * 4] =
            *(const float4*)&g_ckv[sidx * HD * HD + lin * 4];
    }
    if (tid < HD) ksum[tid] = g_cks[sidx * HD + tid];
    __syncthreads();

    // ---- stage 1: S = mask(Q K^T), 4x4 tile per thread ----
    {
        int i0 = ty * 4, j0 = tx * 4;
        float s[4][4];
#pragma unroll
        for (int i = 0; i < 4; i++)
#pragma unroll
            for (int j = 0; j < 4; j++) s[i][j] = 0.f;

#pragma unroll 8
        for (int d = 0; d < HD; d++) {
            float4 q0 = *(const float4*)&Qt[d * SP + i0];
            float4 k0 = *(const float4*)&Kt[d * SP + j0];
            float qa[4] = {q0.x, q0.y, q0.z, q0.w};
            float kb[4] = {k0.x, k0.y, k0.z, k0.w};
#pragma unroll
            for (int i = 0; i < 4; i++)
#pragma unroll
                for (int j = 0; j < 4; j++) s[i][j] += qa[i] * kb[j];
        }
#pragma unroll
        for (int ii = 0; ii < 4; ii++) {
            int i = i0 + ii;
            float4 o0;
            o0.x = (j0 + 0 <= i) ? s[ii][0] : 0.f;
            o0.y = (j0 + 1 <= i) ? s[ii][1] : 0.f;
            o0.z = (j0 + 2 <= i) ? s[ii][2] : 0.f;
            o0.w = (j0 + 3 <= i) ? s[ii][3] : 0.f;
            *(float4*)&S[i * SP + j0] = o0;
        }
    }
    __syncthreads();

    // ---- stage 2: O = S V + Q KVp ; denom ; split-store for O-proj ----
    {
        int i0 = ty * 4, m0 = tx * 4;
        float acc[4][4];
        float rs[4];
#pragma unroll
        for (int i = 0; i < 4; i++) {
            rs[i] = 0.f;
#pragma unroll
            for (int j = 0; j < 4; j++) acc[i][j] = 0.f;
        }

#pragma unroll 4
        for (int j = 0; j < CHUNK; j++) {
            float4 vv = *(const float4*)&V[j * SP + m0];
            float va[4] = {vv.x, vv.y, vv.z, vv.w};
#pragma unroll
            for (int ii = 0; ii < 4; ii++) {
                float sv = S[(i0 + ii) * SP + j];
                rs[ii] += sv;
#pragma unroll
                for (int mm = 0; mm < 4; mm++) acc[ii][mm] += sv * va[mm];
            }
        }
#pragma unroll 4
        for (int d = 0; d < HD; d++) {
            float4 q0 = *(const float4*)&Qt[d * SP + i0];
            float qa[4] = {q0.x, q0.y, q0.z, q0.w};
            float4 kv = *(const float4*)&KVp[d * SP + m0];
            float ka[4] = {kv.x, kv.y, kv.z, kv.w};
            float kss = ksum[d];
#pragma unroll
            for (int ii = 0; ii < 4; ii++) {
                rs[ii] += qa[ii] * kss;
#pragma unroll
                for (int mm = 0; mm < 4; mm++) acc[ii][mm] += qa[ii] * ka[mm];
            }
        }
        if (tx == 0) {
#pragma unroll
            for (int ii = 0; ii < 4; ii++) dn[i0 + ii] = rs[ii];
        }
        __syncthreads();
#pragma unroll
        for (int ii = 0; ii < 4; ii++) {
            float inv = 1.f / fmaxf(dn[i0 + ii], 1e-6f);
            size_t g = (nbase + i0 + ii) * D + h * HD + m0;
            uint16_t hh[4], ll[4];
#pragma unroll
            for (int mm = 0; mm < 4; mm++)
                split2(acc[ii][mm] * inv, hh[mm], ll[mm]);
            *(uint2*)&g_phi[g] = make_uint2((uint32_t)hh[0] | ((uint32_t)hh[1] << 16),
                                            (uint32_t)hh[2] | ((uint32_t)hh[3] << 16));
            *(uint2*)&g_plo[g] = make_uint2((uint32_t)ll[0] | ((uint32_t)ll[1] << 16),
                                            (uint32_t)ll[2] | ((uint32_t)ll[3] << 16));
        }
    }
}

// ---------------- launch ----------------
extern "C" void kernel_launch(void* const* d_in, const int* in_sizes, int n_in,
                              void* d_out, int out_size)
{
    const float* x  = (const float*)d_in[0];
    const float* Wq = (const float*)d_in[1];
    const float* bq = (const float*)d_in[2];
    const float* Wk = (const float*)d_in[3];
    const float* bk = (const float*)d_in[4];
    const float* Wv = (const float*)d_in[5];
    const float* bv = (const float*)d_in[6];
    const float* Wo = (const float*)d_in[7];
    const float* bo = (const float*)d_in[8];

    int N = in_sizes[0] / D;     // b * t
    int B = N / TSEQ;
    int rowTiles = N / 128;

    cudaFuncSetAttribute(mma_gemm,
                         cudaFuncAttributeMaxDynamicSharedMemorySize, GEMM_SMEM);
    cudaFuncSetAttribute(chunk_sum_kernel,
                         cudaFuncAttributeMaxDynamicSharedMemorySize,
                         2 * CHUNK * HD * (int)sizeof(float));
    cudaFuncSetAttribute(attn_chunk_kernel,
                         cudaFuncAttributeMaxDynamicSharedMemorySize,
                         SM2C_FLOATS * (int)sizeof(float));

    // split conversions: weights + x
    convert_w<<<(4 * D * D / 4) / 256, 256>>>(Wq, Wk, Wv, Wo);
    convert_x<<<(N * D / 4 + 255) / 256, 256>>>(x, N * D / 4);

    // fused QKV projection (z = 0,1,2 -> q,k,v); elu+1 on q,k
    dim3 gq(D / 128, rowTiles, 3);
    mma_gemm<<<gq, 256, GEMM_SMEM>>>(0, 0, 0, bq, bk, bv, nullptr, 0x3);

    chunk_sum_kernel<<<dim3(B * NC, HEADS), 512,
                       2 * CHUNK * HD * sizeof(float)>>>();
    prefix_kernel<<<B * HEADS, 256>>>();
    attn_chunk_kernel<<<dim3(B * NC, HEADS), 256,
                        SM2C_FLOATS * sizeof(float)>>>();

    // output projection from split attention output -> d_out
    dim3 go(D / 128, rowTiles, 1);
    mma_gemm<<<go, 256, GEMM_SMEM>>>(1, 3, 3, bo, bo, bo, (float*)d_out, 0x0);
}

// round 9
// speedup vs baseline: 3.3677x; 1.0176x over previous
#include <cuda_runtime.h>
#include <cuda_bf16.h>
#include <cstdint>

#define D 512
#define HEADS 8
#define HD 64
#define TSEQ 1024
#define CHUNK 64
#define NC (TSEQ / CHUNK)   // 16
#define MAXB 4

// ---------------- scratch (no allocations allowed) ----------------
__device__ float g_q[MAXB * TSEQ * D];
__device__ float g_k[MAXB * TSEQ * D];
__device__ float g_v[MAXB * TSEQ * D];
__device__ float g_ckv[MAXB * HEADS * NC * HD * HD];
__device__ float g_cks[MAXB * HEADS * NC * HD];
// bf16 split operands
__device__ __nv_bfloat16 g_whi[4 * D * D];
__device__ __nv_bfloat16 g_wlo[4 * D * D];
__device__ __nv_bfloat16 g_xhi[MAXB * TSEQ * D];
__device__ __nv_bfloat16 g_xlo[MAXB * TSEQ * D];
__device__ __nv_bfloat16 g_phi[MAXB * TSEQ * D];   // post-attention activations
__device__ __nv_bfloat16 g_plo[MAXB * TSEQ * D];

// ---------------- helpers ----------------
__device__ __forceinline__ void split2(float f, uint16_t& h, uint16_t& l) {
    __nv_bfloat16 hb = __float2bfloat16_rn(f);
    float hf = __bfloat162float(hb);
    __nv_bfloat16 lb = __float2bfloat16_rn(f - hf);
    h = __bfloat16_as_ushort(hb);
    l = __bfloat16_as_ushort(lb);
}

__device__ __forceinline__ void mma_bf16(float* d, const uint32_t* a, const uint32_t* b) {
    asm volatile(
        "mma.sync.aligned.m16n8k16.row.col.f32.bf16.bf16.f32 "
        "{%0,%1,%2,%3}, {%4,%5,%6,%7}, {%8,%9}, {%0,%1,%2,%3};"
        : "+f"(d[0]), "+f"(d[1]), "+f"(d[2]), "+f"(d[3])
        : "r"(a[0]), "r"(a[1]), "r"(a[2]), "r"(a[3]), "r"(b[0]), "r"(b[1]));
}

__device__ __forceinline__ uint32_t smem_u32(const void* p) {
    uint32_t a;
    asm("{ .reg .u64 t; cvta.to.shared.u64 t, %1; cvt.u32.u64 %0, t; }"
        : "=r"(a) : "l"(p));
    return a;
}
__device__ __forceinline__ void cp16(uint32_t dst, const void* src) {
    asm volatile("cp.async.cg.shared.global [%0], [%1], 16;"
                 :: "r"(dst), "l"(src));
}
#define CP_COMMIT() asm volatile("cp.async.commit_group;" ::: "memory")
#define CP_WAIT(n)  asm volatile("cp.async.wait_group %0;" :: "n"(n) : "memory")

#define LDSM4(r, addr) \
    asm volatile("ldmatrix.sync.aligned.m8n8.x4.shared.b16 {%0,%1,%2,%3}, [%4];" \
        : "=r"((r)[0]), "=r"((r)[1]), "=r"((r)[2]), "=r"((r)[3]) : "r"(addr))

// ---------------- conversion kernels ----------------
__global__ void __launch_bounds__(256) convert_w(
    const float* __restrict__ Wq, const float* __restrict__ Wk,
    const float* __restrict__ Wv, const float* __restrict__ Wo)
{
    int e4 = blockIdx.x * 256 + threadIdx.x;       // 0..262143 (4 * 65536)
    int w = e4 >> 16;
    int off = e4 & 65535;
    const float* src = (w == 0) ? Wq : (w == 1) ? Wk : (w == 2) ? Wv : Wo;
    float4 v = ((const float4*)src)[off];
    float f[4] = {v.x, v.y, v.z, v.w};
    uint16_t h[4], l[4];
#pragma unroll
    for (int j = 0; j < 4; ++j) split2(f[j], h[j], l[j]);
    ((uint2*)(g_whi + (size_t)w * D * D))[off] =
        make_uint2((uint32_t)h[0] | ((uint32_t)h[1] << 16),
                   (uint32_t)h[2] | ((uint32_t)h[3] << 16));
    ((uint2*)(g_wlo + (size_t)w * D * D))[off] =
        make_uint2((uint32_t)l[0] | ((uint32_t)l[1] << 16),
                   (uint32_t)l[2] | ((uint32_t)l[3] << 16));
}

__global__ void __launch_bounds__(256) convert_x(const float* __restrict__ src, int n4)
{
    int i = blockIdx.x * 256 + threadIdx.x;
    if (i >= n4) return;
    float4 v = ((const float4*)src)[i];
    float f[4] = {v.x, v.y, v.z, v.w};
    uint16_t h[4], l[4];
#pragma unroll
    for (int j = 0; j < 4; ++j) split2(f[j], h[j], l[j]);
    ((uint2*)g_xhi)[i] = make_uint2((uint32_t)h[0] | ((uint32_t)h[1] << 16),
                                    (uint32_t)h[2] | ((uint32_t)h[3] << 16));
    ((uint2*)g_xlo)[i] = make_uint2((uint32_t)l[0] | ((uint32_t)l[1] << 16),
                                    (uint32_t)l[2] | ((uint32_t)l[3] << 16));
}

// ---------------- mma.sync split-bf16 GEMM (cp.async + ldmatrix) ----------------
#define ROWU 36
#define ARRU (128 * ROWU)      // 4608
#define BUFU (4 * ARRU)        // 18432
#define GEMM_SMEM (2 * BUFU * 4)   // 147456 bytes

// async copy one K-chunk (A/B hi/lo) into smem buffer at byte base sbB
__device__ __forceinline__ void load_chunk_async(
    uint32_t sbB, const uint32_t* Ahi, const uint32_t* Alo,
    const uint32_t* Bhi, const uint32_t* Blo,
    int rowBase, int colBase, int k0u, int tid)
{
#pragma unroll
    for (int it = 0; it < 4; ++it) {
        int lin = tid + it * 256;          // 0..1023
        int r = lin >> 3, q = lin & 7;
        uint32_t dOff = (uint32_t)(r * ROWU + q * 4) * 4;
        cp16(sbB + dOff, Ahi + (size_t)(rowBase + r) * 256 + k0u + q * 4);
        cp16(sbB + ARRU * 4 + dOff, Alo + (size_t)(rowBase + r) * 256 + k0u + q * 4);
        cp16(sbB + 2 * ARRU * 4 + dOff, Bhi + (size_t)(colBase + r) * 256 + k0u + q * 4);
        cp16(sbB + 3 * ARRU * 4 + dOff, Blo + (size_t)(colBase + r) * 256 + k0u + q * 4);
    }
}

__global__ void __launch_bounds__(256, 1) mma_gemm(
    int asel, int wBase, int oselBase,
    const float* __restrict__ bias0, const float* __restrict__ bias1,
    const float* __restrict__ bias2,
    float* __restrict__ Oext, int actmask)
{
    extern __shared__ __align__(16) uint32_t smu[];
    int tid = threadIdx.x, lane = tid & 31, wid = tid >> 5;
    int warpRow = wid >> 2;
    int warpCol = wid & 3;
    int z = blockIdx.z;
    int rowBase = blockIdx.y * 128;
    int colBase = blockIdx.x * 128;

    const uint32_t* Ahi = asel ? (const uint32_t*)g_phi : (const uint32_t*)g_xhi;
    const uint32_t* Alo = asel ? (const uint32_t*)g_plo : (const uint32_t*)g_xlo;
    int wz = wBase + z;
    const uint32_t* Bhi = (const uint32_t*)g_whi + (size_t)wz * (D * D / 2);
    const uint32_t* Blo = (const uint32_t*)g_wlo + (size_t)wz * (D * D / 2);
    const float* bias = (z == 0) ? bias0 : (z == 1) ? bias1 : bias2;
    int osel = oselBase + z;
    float* O = (osel == 3) ? Oext : (osel == 0 ? g_q : (osel == 1 ? g_k : g_v));
    int act = (actmask >> z) & 1;

    uint32_t sbB = smem_u32(smu);

    // ldmatrix lane addressing (verified against scalar fragment mapping):
    // A x4: lanes 0-7 rows0-7/k0-7, 8-15 rows8-15/k0-7, 16-23 rows0-7/k8-15,
    //       24-31 rows8-15/k8-15  -> regs a0,a1,a2,a3
    int lrA = lane & 15, lhA = lane >> 4;
    // B x4 (two n8 tiles): lanes 0-7 n0-7/k0-7, 8-15 n0-7/k8-15,
    //       16-23 n8-15/k0-7, 24-31 n8-15/k8-15 -> regs b0(nt0),b1(nt0),b0(nt1),b1(nt1)
    int brB = ((lane >> 4) << 3) + (lane & 7);
    int bhB = (lane >> 3) & 1;

    float acc[4][4][4];
#pragma unroll
    for (int mt = 0; mt < 4; ++mt)
#pragma unroll
        for (int nt = 0; nt < 4; ++nt)
#pragma unroll
            for (int r = 0; r < 4; ++r) acc[mt][nt][r] = 0.f;

    load_chunk_async(sbB, Ahi, Alo, Bhi, Blo, rowBase, colBase, 0, tid);
    CP_COMMIT();

    for (int c = 0; c < 8; ++c) {
        int buf = c & 1;
        if (c < 7) {
            load_chunk_async(sbB + ((c + 1) & 1) * BUFU * 4,
                             Ahi, Alo, Bhi, Blo, rowBase, colBase,
                             (c + 1) * 32, tid);
            CP_COMMIT();
            CP_WAIT(1);             // chunk c complete, c+1 in flight
        } else {
            CP_WAIT(0);             // last chunk complete
        }
        __syncthreads();

        uint32_t aBH = sbB + (uint32_t)buf * BUFU * 4;
        uint32_t aBL = aBH + ARRU * 4;
        uint32_t bBH = aBH + 2 * ARRU * 4;
        uint32_t bBL = aBH + 3 * ARRU * 4;
#pragma unroll
        for (int ks = 0; ks < 4; ++ks) {
            uint32_t ahi[4][4], alo[4][4], bhi[4][2], blo[4][2];
#pragma unroll
            for (int mt = 0; mt < 4; ++mt) {
                uint32_t off = (uint32_t)((warpRow * 64 + mt * 16 + lrA) * ROWU
                                          + ks * 8 + lhA * 4) * 4;
                LDSM4(ahi[mt], aBH + off);
                LDSM4(alo[mt], aBL + off);
            }
#pragma unroll
            for (int p = 0; p < 2; ++p) {
                uint32_t off = (uint32_t)((warpCol * 32 + p * 16 + brB) * ROWU
                                          + ks * 8 + bhB * 4) * 4;
                uint32_t t0[4], t1[4];
                LDSM4(t0, bBH + off);
                LDSM4(t1, bBL + off);
                bhi[2 * p][0] = t0[0]; bhi[2 * p][1] = t0[1];
                bhi[2 * p + 1][0] = t0[2]; bhi[2 * p + 1][1] = t0[3];
                blo[2 * p][0] = t1[0]; blo[2 * p][1] = t1[1];
                blo[2 * p + 1][0] = t1[2]; blo[2 * p + 1][1] = t1[3];
            }
#pragma unroll
            for (int mt = 0; mt < 4; ++mt)
#pragma unroll
                for (int nt = 0; nt < 4; ++nt) {
                    mma_bf16(acc[mt][nt], ahi[mt], bhi[nt]);
                    mma_bf16(acc[mt][nt], ahi[mt], blo[nt]);
                    mma_bf16(acc[mt][nt], alo[mt], bhi[nt]);
                }
        }
        __syncthreads();
    }

#pragma unroll
    for (int mt = 0; mt < 4; ++mt) {
        int r0 = rowBase + warpRow * 64 + mt * 16 + (lane >> 2);
#pragma unroll
        for (int nt = 0; nt < 4; ++nt) {
            int cc = colBase + warpCol * 32 + nt * 8 + (lane & 3) * 2;
            float b0 = bias[cc], b1 = bias[cc + 1];
            float v0 = acc[mt][nt][0] + b0;
            float v1 = acc[mt][nt][1] + b1;
            float v2 = acc[mt][nt][2] + b0;
            float v3 = acc[mt][nt][3] + b1;
            if (act) {
                v0 = (v0 > 0.f) ? v0 + 1.f : __expf(v0);
                v1 = (v1 > 0.f) ? v1 + 1.f : __expf(v1);
                v2 = (v2 > 0.f) ? v2 + 1.f : __expf(v2);
                v3 = (v3 > 0.f) ? v3 + 1.f : __expf(v3);
            }
            *(float2*)&O[(size_t)r0 * D + cc] = make_float2(v0, v1);
            *(float2*)&O[(size_t)(r0 + 8) * D + cc] = make_float2(v2, v3);
        }
    }
}

// ---------------- per-chunk local sums (CHUNK=64, m-split x2) ----------------
// grid (B*NC, HEADS*2): blockIdx.y = h*2 + mhalf; CTA computes KV[64][32].
__global__ void __launch_bounds__(256) chunk_sum_kernel()
{
    int bc = blockIdx.x;            // b*NC + c
    int hm = blockIdx.y;
    int h = hm >> 1, mh = hm & 1;
    int b = bc / NC, c = bc % NC;
    extern __shared__ __align__(16) float smf[];
    float* ks = smf;                   // [CHUNK][HD]
    float* vs = smf + CHUNK * HD;      // [CHUNK][32]

    int tid = threadIdx.x;
    size_t nbase = (size_t)b * TSEQ + (size_t)c * CHUNK;

#pragma unroll
    for (int it = 0; it < 4; it++) {
        int lin = tid + it * 256;   // float4 index, 1024 total
        int t = lin >> 4;
        int d4 = lin & 15;
        ((float4*)ks)[lin] = *(const float4*)&g_k[(nbase + t) * D + h * HD + d4 * 4];
    }
#pragma unroll
    for (int it = 0; it < 2; it++) {
        int lin = tid + it * 256;   // float4 index, 512 total
        int t = lin >> 3;
        int m4 = lin & 7;
        ((float4*)vs)[lin] =
            *(const float4*)&g_v[(nbase + t) * D + h * HD + mh * 32 + m4 * 4];
    }
    __syncthreads();

    int d0 = (tid >> 4) * 4;       // 0..60
    int m0 = (tid & 15) * 2;       // 0..30
    float acc[4][2];
#pragma unroll
    for (int i = 0; i < 4; i++) { acc[i][0] = 0.f; acc[i][1] = 0.f; }

#pragma unroll 8
    for (int t = 0; t < CHUNK; t++) {
        float4 kd = *(const float4*)&ks[t * HD + d0];
        float2 vm = *(const float2*)&vs[t * 32 + m0];
        float ka[4] = {kd.x, kd.y, kd.z, kd.w};
#pragma unroll
        for (int i = 0; i < 4; i++) {
            acc[i][0] += ka[i] * vm.x;
            acc[i][1] += ka[i] * vm.y;
        }
    }

    size_t sidx = ((size_t)(b * HEADS + h) * NC + c);
    float* ckv = g_ckv + sidx * HD * HD;
#pragma unroll
    for (int i = 0; i < 4; i++)
        *(float2*)&ckv[(d0 + i) * HD + mh * 32 + m0] = make_float2(acc[i][0], acc[i][1]);

    if (mh == 0 && tid < HD) {
        float s = 0.f;
#pragma unroll 8
        for (int t = 0; t < CHUNK; t++) s += ks[t * HD + tid];
        g_cks[sidx * HD + tid] = s;
    }
}
#define CS_SMEM ((CHUNK * HD + CHUNK * 32) * 4)   // 24576 B

// ---------------- exclusive prefix over chunks per (b,h) ----------------
__global__ void __launch_bounds__(256) prefix_kernel()
{
    int bh = blockIdx.x;
    int tid = threadIdx.x;
    float* base = g_ckv + (size_t)bh * NC * HD * HD;
    for (int e = tid; e < HD * HD; e += 256) {
        float carry = 0.f;
#pragma unroll
        for (int c = 0; c < NC; c++) {
            float tv = base[c * HD * HD + e];
            base[c * HD * HD + e] = carry;
            carry += tv;
        }
    }
    if (tid < HD) {
        float* kb = g_cks + (size_t)bh * NC * HD;
        float carry = 0.f;
#pragma unroll
        for (int c = 0; c < NC; c++) {
            float tv = kb[c * HD + tid];
            kb[c * HD + tid] = carry;
            carry += tv;
        }
    }
}

// ---------------- per-chunk attention (CHUNK=64) ----------------
// S = mask(Q Kt), O = S V + Q KVp, denom = rowsum(S) + Q . ksum
#define SP 68
#define QT_OFF 0
#define KT_OFF (HD * SP)                 // 4352
#define V_OFF  (KT_OFF + HD * SP)        // 8704
#define S_OFF  (V_OFF + CHUNK * SP)      // 13056
#define KVP_OFF (S_OFF + CHUNK * SP)     // 17408
#define KS_OFF (KVP_OFF + HD * SP)       // 21760
#define DN_OFF (KS_OFF + HD)             // 21824
#define SM2C_FLOATS (DN_OFF + CHUNK)     // 21888 floats = 87552 B

__global__ void __launch_bounds__(256) attn_chunk_kernel()
{
    int bc = blockIdx.x;
    int h = blockIdx.y;
    int b = bc / NC, c = bc % NC;
    extern __shared__ __align__(16) float smf[];
    float* Qt = smf + QT_OFF;     // [HD][SP]  (transposed: [d][i])
    float* Kt = smf + KT_OFF;     // [HD][SP]
    float* V  = smf + V_OFF;      // [CHUNK][SP]
    float* S  = smf + S_OFF;      // [CHUNK][SP] row-major [i][j]
    float* KVp = smf + KVP_OFF;   // [HD][SP]
    float* ksum = smf + KS_OFF;   // [HD]
    float* dn = smf + DN_OFF;     // [CHUNK]

    int tid = threadIdx.x;
    int tx = tid & 15, ty = tid >> 4;
    size_t nbase = (size_t)b * TSEQ + (size_t)c * CHUNK;
    size_t sidx = ((size_t)(b * HEADS + h) * NC + c);

    // loads (coalesced global, transposed store for Q/K)
#pragma unroll
    for (int it = 0; it < 16; it++) {
        int lin = tid + it * 256;    // 4096
        int i = lin >> 6, d = lin & 63;
        size_t g = (nbase + i) * D + h * HD + d;
        Qt[d * SP + i] = g_q[g];
        Kt[d * SP + i] = g_k[g];
    }
#pragma unroll
    for (int it = 0; it < 4; it++) {
        int lin = tid + it * 256;    // float4, 1024
        int i = lin >> 4, d4 = lin & 15;
        *(float4*)&V[i * SP + d4 * 4] =
            *(const float4*)&g_v[(nbase + i) * D + h * HD + d4 * 4];
    }
#pragma unroll
    for (int it = 0; it < 4; it++) {
        int lin = tid + it * 256;    // float4, 1024
        int dd = lin >> 4, m4 = lin & 15;
        *(float4*)&KVp[dd * SP + m4 * 4] =
            *(const float4*)&g_ckv[sidx * HD * HD + lin * 4];
    }
    if (tid < HD) ksum[tid] = g_cks[sidx * HD + tid];
    __syncthreads();

    // ---- stage 1: S = mask(Q K^T), 4x4 tile per thread ----
    {
        int i0 = ty * 4, j0 = tx * 4;
        float s[4][4];
#pragma unroll
        for (int i = 0; i < 4; i++)
#pragma unroll
            for (int j = 0; j < 4; j++) s[i][j] = 0.f;

#pragma unroll 8
        for (int d = 0; d < HD; d++) {
            float4 q0 = *(const float4*)&Qt[d * SP + i0];
            float4 k0 = *(const float4*)&Kt[d * SP + j0];
            float qa[4] = {q0.x, q0.y, q0.z, q0.w};
            float kb[4] = {k0.x, k0.y, k0.z, k0.w};
#pragma unroll
            for (int i = 0; i < 4; i++)
#pragma unroll
                for (int j = 0; j < 4; j++) s[i][j] += qa[i] * kb[j];
        }
#pragma unroll
        for (int ii = 0; ii < 4; ii++) {
            int i = i0 + ii;
            float4 o0;
            o0.x = (j0 + 0 <= i) ? s[ii][0] : 0.f;
            o0.y = (j0 + 1 <= i) ? s[ii][1] : 0.f;
            o0.z = (j0 + 2 <= i) ? s[ii][2] : 0.f;
            o0.w = (j0 + 3 <= i) ? s[ii][3] : 0.f;
            *(float4*)&S[i * SP + j0] = o0;
        }
    }
    __syncthreads();

    // ---- stage 2: O = S V + Q KVp ; denom ; split-store for O-proj ----
    {
        int i0 = ty * 4, m0 = tx * 4;
        float acc[4][4];
        float rs[4];
#pragma unroll
        for (int i = 0; i < 4; i++) {
            rs[i] = 0.f;
#pragma unroll
            for (int j = 0; j < 4; j++) acc[i][j] = 0.f;
        }

#pragma unroll 4
        for (int j = 0; j < CHUNK; j++) {
            float4 vv = *(const float4*)&V[j * SP + m0];
            float va[4] = {vv.x, vv.y, vv.z, vv.w};
#pragma unroll
            for (int ii = 0; ii < 4; ii++) {
                float sv = S[(i0 + ii) * SP + j];
                rs[ii] += sv;
#pragma unroll
                for (int mm = 0; mm < 4; mm++) acc[ii][mm] += sv * va[mm];
            }
        }
#pragma unroll 4
        for (int d = 0; d < HD; d++) {
            float4 q0 = *(const float4*)&Qt[d * SP + i0];
            float qa[4] = {q0.x, q0.y, q0.z, q0.w};
            float4 kv = *(const float4*)&KVp[d * SP + m0];
            float ka[4] = {kv.x, kv.y, kv.z, kv.w};
            float kss = ksum[d];
#pragma unroll
            for (int ii = 0; ii < 4; ii++) {
                rs[ii] += qa[ii] * kss;
#pragma unroll
                for (int mm = 0; mm < 4; mm++) acc[ii][mm] += qa[ii] * ka[mm];
            }
        }
        if (tx == 0) {
#pragma unroll
            for (int ii = 0; ii < 4; ii++) dn[i0 + ii] = rs[ii];
        }
        __syncthreads();
#pragma unroll
        for (int ii = 0; ii < 4; ii++) {
            float inv = 1.f / fmaxf(dn[i0 + ii], 1e-6f);
            size_t g = (nbase + i0 + ii) * D + h * HD + m0;
            uint16_t hh[4], ll[4];
#pragma unroll
            for (int mm = 0; mm < 4; mm++)
                split2(acc[ii][mm] * inv, hh[mm], ll[mm]);
            *(uint2*)&g_phi[g] = make_uint2((uint32_t)hh[0] | ((uint32_t)hh[1] << 16),
                                            (uint32_t)hh[2] | ((uint32_t)hh[3] << 16));
            *(uint2*)&g_plo[g] = make_uint2((uint32_t)ll[0] | ((uint32_t)ll[1] << 16),
                                            (uint32_t)ll[2] | ((uint32_t)ll[3] << 16));
        }
    }
}

// ---------------- launch ----------------
extern "C" void kernel_launch(void* const* d_in, const int* in_sizes, int n_in,
                              void* d_out, int out_size)
{
    const float* x  = (const float*)d_in[0];
    const float* Wq = (const float*)d_in[1];
    const float* bq = (const float*)d_in[2];
    const float* Wk = (const float*)d_in[3];
    const float* bk = (const float*)d_in[4];
    const float* Wv = (const float*)d_in[5];
    const float* bv = (const float*)d_in[6];
    const float* Wo = (const float*)d_in[7];
    const float* bo = (const float*)d_in[8];

    int N = in_sizes[0] / D;     // b * t
    int B = N / TSEQ;
    int rowTiles = N / 128;

    cudaFuncSetAttribute(mma_gemm,
                         cudaFuncAttributeMaxDynamicSharedMemorySize, GEMM_SMEM);
    cudaFuncSetAttribute(attn_chunk_kernel,
                         cudaFuncAttributeMaxDynamicSharedMemorySize,
                         SM2C_FLOATS * (int)sizeof(float));

    // split conversions: weights + x
    convert_w<<<(4 * D * D / 4) / 256, 256>>>(Wq, Wk, Wv, Wo);
    convert_x<<<(N * D / 4 + 255) / 256, 256>>>(x, N * D / 4);

    // fused QKV projection (z = 0,1,2 -> q,k,v); elu+1 on q,k
    dim3 gq(D / 128, rowTiles, 3);
    mma_gemm<<<gq, 256, GEMM_SMEM>>>(0, 0, 0, bq, bk, bv, nullptr, 0x3);

    chunk_sum_kernel<<<dim3(B * NC, HEADS * 2), 256, CS_SMEM>>>();
    prefix_kernel<<<B * HEADS, 256>>>();
    attn_chunk_kernel<<<dim3(B * NC, HEADS), 256,
                        SM2C_FLOATS * sizeof(float)>>>();

    // output projection from split attention output -> d_out
    dim3 go(D / 128, rowTiles, 1);
    mma_gemm<<<go, 256, GEMM_SMEM>>>(1, 3, 3, bo, bo, bo, (float*)d_out, 0x0);
}